// round 5
// baseline (speedup 1.0000x reference)
#include <cuda_runtime.h>
#include <cuda_bf16.h>
#include <math.h>
#include <stdint.h>

// ---------------- constants ----------------
#define Hdim 768
#define NH 12
#define NKV 4
#define HD 64
#define IM 3072
#define KCONV 4
#define SEQ 1024
#define BATCH 2
#define ROWS (BATCH*SEQ)      // 2048
#define VOCAB 50304
#define H3 (3*Hdim)           // 2304
#define QKVN 1280             // 768 + 256 + 256
#define GUN  (2*IM)           // 6144

// gemm tiling
#define BK 32
#define SSTR 40                       // padded row stride (bf16) -> conflict-free ldmatrix
#define ARRB (128*SSTR*2)             // 10240 bytes per operand array
#define STAGEB (4*ARRB)               // 40960 per stage (Ah,Al,Bh,Bl)
#define NST 4
#define GSMEM (NST*STAGEB)            // 163840

// ---------------- packed weight offsets (elems) ----------------
#define OFF_QKV  0ull                  // [4][1280][768]
#define OFF_OW   3932160ull            // [4][768][768]
#define OFF_AGU  6291456ull            // [4][6144][768]
#define OFF_AD   25165824ull           // [4][768][3072]
#define OFF_INW  34603008ull           // [8][2304][768]
#define OFF_OUTW 48758784ull           // [8][768][768]
#define OFF_CGU  53477376ull           // [8][6144][768]
#define OFF_CD   91226112ull           // [8][768][3072]
#define OFF_LM   110100480ull          // [50304][768]
#define W_TOTAL  148733952ull

// ---------------- scratch (device globals; no allocation) ----------------
__device__ float g_x  [ROWS*Hdim];
__device__ float g_qkv[ROWS*QKVN];
__device__ float g_t1 [ROWS*H3];
__device__ float g_t12[ROWS*GUN];
__device__ __nv_bfloat16 g_ah[ROWS*IM];
__device__ __nv_bfloat16 g_al[ROWS*IM];
__device__ __nv_bfloat16 g_wh[W_TOTAL];
__device__ __nv_bfloat16 g_wl[W_TOTAL];

// ---------------- helpers ----------------
__device__ __forceinline__ void split1(float x, __nv_bfloat16* h, __nv_bfloat16* l) {
    __nv_bfloat16 hh = __float2bfloat16(x);
    *h = hh;
    *l = __float2bfloat16(x - __bfloat162float(hh));
}
__device__ __forceinline__ unsigned cvta_s(const void* p) {
    return (unsigned)__cvta_generic_to_shared(p);
}
__device__ __forceinline__ void cp16(unsigned saddr, const void* g) {
    asm volatile("cp.async.cg.shared.global [%0], [%1], 16;\n" :: "r"(saddr), "l"(g));
}
__device__ __forceinline__ void ldm4(unsigned* r, unsigned addr) {
    asm volatile("ldmatrix.sync.aligned.m8n8.x4.shared.b16 {%0,%1,%2,%3}, [%4];\n"
                 : "=r"(r[0]), "=r"(r[1]), "=r"(r[2]), "=r"(r[3]) : "r"(addr));
}
__device__ __forceinline__ void mma16816(float* d, const unsigned* a, const unsigned* b) {
    asm volatile("mma.sync.aligned.m16n8k16.row.col.f32.bf16.bf16.f32 "
                 "{%0,%1,%2,%3}, {%4,%5,%6,%7}, {%8,%9}, {%0,%1,%2,%3};\n"
                 : "+f"(d[0]), "+f"(d[1]), "+f"(d[2]), "+f"(d[3])
                 : "r"(a[0]), "r"(a[1]), "r"(a[2]), "r"(a[3]), "r"(b[0]), "r"(b[1]));
}

// ======================= 4-stage multistage bf16x3 GEMM =======================
// C[M,N] = A*B^T (+bias)(+res). A,B as (hi,lo) bf16, K-major, K%32==0.
// Tile 128x128x32, 256 threads, warp tile 32x64. grid.x = M/128 (fast dim).
__global__ void __launch_bounds__(256) gemm_ms(
    const __nv_bfloat16* __restrict__ Ah, const __nv_bfloat16* __restrict__ Al,
    const __nv_bfloat16* __restrict__ Bh, const __nv_bfloat16* __restrict__ Bl,
    float* __restrict__ C, int M, int N, int K,
    const float* __restrict__ bias, const float* __restrict__ res)
{
    extern __shared__ __align__(16) char sm_raw[];
    const int tid = threadIdx.x;
    const int lane = tid & 31, wid = tid >> 5;
    const int wm = wid >> 1, wn = wid & 1;
    const int bm = blockIdx.x * 128, bn = blockIdx.y * 128;
    const unsigned sbase = cvta_s(sm_raw);

    const __nv_bfloat16* gp[4] = {
        Ah + (size_t)bm * K, Al + (size_t)bm * K,
        Bh + (size_t)bn * K, Bl + (size_t)bn * K };

    float acc[2][8][4];
    #pragma unroll
    for (int t = 0; t < 2; t++)
        #pragma unroll
        for (int n = 0; n < 8; n++)
            #pragma unroll
            for (int i = 0; i < 4; i++) acc[t][n][i] = 0.f;

    auto load_chunk = [&](int st, int c) {
        int gk = c * BK;
        #pragma unroll
        for (int i = 0; i < 8; i++) {
            int idx = tid + i * 256;          // 0..2047
            int arr = idx >> 9;               // 0..3
            int j = idx & 511;
            int row = j >> 2, c4 = j & 3;
            cp16(sbase + st * STAGEB + arr * ARRB + (unsigned)(row * SSTR + c4 * 8) * 2,
                 gp[arr] + (size_t)row * K + gk + c4 * 8);
        }
        asm volatile("cp.async.commit_group;\n");
    };

    const int nk = K / BK;
    #pragma unroll
    for (int s = 0; s < NST - 1; s++) load_chunk(s, s);

    for (int c = 0; c < nk; c++) {
        asm volatile("cp.async.wait_group %0;\n" :: "n"(NST - 2));
        __syncthreads();
        if (c + NST - 1 < nk) load_chunk((c + NST - 1) % NST, c + NST - 1);
        else asm volatile("cp.async.commit_group;\n");

        unsigned st = sbase + (c % NST) * STAGEB;
        #pragma unroll
        for (int kk = 0; kk < BK; kk += 16) {
            unsigned ah[2][4], al[2][4], bh[8][2], bl[8][2];
            #pragma unroll
            for (int t = 0; t < 2; t++) {
                int row = wm * 32 + t * 16 + (lane & 15);
                int col = kk + ((lane >> 4) << 3);
                unsigned off = (unsigned)(row * SSTR + col) * 2;
                ldm4(ah[t], st + off);
                ldm4(al[t], st + ARRB + off);
            }
            #pragma unroll
            for (int p = 0; p < 4; p++) {
                int m = lane >> 3;
                int row = wn * 64 + p * 16 + ((m >> 1) << 3) + (lane & 7);
                int col = kk + ((m & 1) << 3);
                unsigned off = (unsigned)(row * SSTR + col) * 2;
                unsigned r[4];
                ldm4(r, st + 2 * ARRB + off);
                bh[2 * p][0] = r[0]; bh[2 * p][1] = r[1];
                bh[2 * p + 1][0] = r[2]; bh[2 * p + 1][1] = r[3];
                ldm4(r, st + 3 * ARRB + off);
                bl[2 * p][0] = r[0]; bl[2 * p][1] = r[1];
                bl[2 * p + 1][0] = r[2]; bl[2 * p + 1][1] = r[3];
            }
            #pragma unroll
            for (int t = 0; t < 2; t++)
                #pragma unroll
                for (int n = 0; n < 8; n++) {
                    mma16816(acc[t][n], ah[t], bh[n]);
                    mma16816(acc[t][n], ah[t], bl[n]);
                    mma16816(acc[t][n], al[t], bh[n]);
                }
        }
    }
    __syncthreads();

    // ---- epilogue: regs -> smem transpose -> coalesced float4 global ----
    float* sC = (float*)sm_raw;                // 128 x 129 floats (66KB <= 160KB)
    #pragma unroll
    for (int t = 0; t < 2; t++) {
        int r0 = wm * 32 + t * 16 + (lane >> 2);
        #pragma unroll
        for (int n = 0; n < 8; n++) {
            int col = wn * 64 + n * 8 + (lane & 3) * 2;
            #pragma unroll
            for (int hh = 0; hh < 2; hh++) {
                sC[(r0 + hh * 8) * 129 + col]     = acc[t][n][hh * 2];
                sC[(r0 + hh * 8) * 129 + col + 1] = acc[t][n][hh * 2 + 1];
            }
        }
    }
    __syncthreads();
    {
        int rr = tid >> 1;
        int ch = (tid & 1) * 64;
        int grow = bm + rr;
        int gcb = bn + ch;
        const float* srow = sC + rr * 129 + ch;
        float* crow = C + (size_t)grow * N + gcb;
        const float* rrow = res ? (res + (size_t)grow * N + gcb) : nullptr;
        #pragma unroll
        for (int i = 0; i < 16; i++) {
            float v0 = srow[4*i], v1 = srow[4*i+1], v2 = srow[4*i+2], v3 = srow[4*i+3];
            if (bias) {
                const float4 bb = *(const float4*)(bias + gcb + 4*i);
                v0 += bb.x; v1 += bb.y; v2 += bb.z; v3 += bb.w;
            }
            if (rrow) {
                const float4 rr4 = *(const float4*)(rrow + 4*i);
                v0 += rr4.x; v1 += rr4.y; v2 += rr4.z; v3 += rr4.w;
            }
            *(float4*)(crow + 4*i) = make_float4(v0, v1, v2, v3);
        }
    }
}

// ---------------- weight split kernel ----------------
__global__ void wsplit_kernel(const float4* __restrict__ X, __nv_bfloat16* __restrict__ H,
                              __nv_bfloat16* __restrict__ L) {
    int idx = blockIdx.x * blockDim.x + threadIdx.x;
    float4 v = X[idx];
    __nv_bfloat16 h[4], l[4];
    split1(v.x, &h[0], &l[0]); split1(v.y, &h[1], &l[1]);
    split1(v.z, &h[2], &l[2]); split1(v.w, &h[3], &l[3]);
    ((__nv_bfloat162*)H)[idx * 2]     = *(__nv_bfloat162*)&h[0];
    ((__nv_bfloat162*)H)[idx * 2 + 1] = *(__nv_bfloat162*)&h[2];
    ((__nv_bfloat162*)L)[idx * 2]     = *(__nv_bfloat162*)&l[0];
    ((__nv_bfloat162*)L)[idx * 2 + 1] = *(__nv_bfloat162*)&l[2];
}

// ---------------- embedding gather ----------------
__global__ void embed_kernel(const int* __restrict__ tok, const float* __restrict__ E,
                             float* __restrict__ X) {
    int row = blockIdx.x;
    int t = tok[row];
    const float* src = E + (size_t)t * Hdim;
    float* dst = X + (size_t)row * Hdim;
    for (int c = threadIdx.x; c < Hdim; c += blockDim.x) dst[c] = src[c];
}

// ---------------- rmsnorm -> bf16 hi/lo ----------------
__global__ void rmsnorm_split_kernel(const float* __restrict__ X, const float* __restrict__ W,
                                     __nv_bfloat16* __restrict__ Hh, __nv_bfloat16* __restrict__ Hl,
                                     int n) {
    int row = blockIdx.x;
    const float* x = X + (size_t)row * n;
    float s = 0.f;
    for (int c = threadIdx.x; c < n; c += blockDim.x) { float v = x[c]; s += v * v; }
    __shared__ float sm[32];
    #pragma unroll
    for (int o = 16; o; o >>= 1) s += __shfl_xor_sync(~0u, s, o);
    if ((threadIdx.x & 31) == 0) sm[threadIdx.x >> 5] = s;
    __syncthreads();
    if (threadIdx.x < 32) {
        float v = (threadIdx.x < (blockDim.x >> 5)) ? sm[threadIdx.x] : 0.f;
        #pragma unroll
        for (int o = 4; o; o >>= 1) v += __shfl_xor_sync(~0u, v, o);
        if (threadIdx.x == 0) sm[0] = v;
    }
    __syncthreads();
    float r = rsqrtf(sm[0] / (float)n + 1e-6f);
    for (int c = threadIdx.x; c < n; c += blockDim.x) {
        float y = x[c] * r * W[c];
        split1(y, &Hh[(size_t)row * n + c], &Hl[(size_t)row * n + c]);
    }
}

// ---------------- per-head RMSNorm (q/k) + RoPE on fused QKV buffer ----------------
__global__ void qknorm_rope_kernel(float* __restrict__ QKV,
                                   const float* __restrict__ qln, const float* __restrict__ kln) {
    int w = threadIdx.x >> 5, l = threadIdx.x & 31;
    int g = blockIdx.x * 8 + w;
    int hh = g & 15;
    int row = g >> 4;
    int s = row & (SEQ - 1);
    float* p; const float* wn;
    if (hh < NH) { p = QKV + (size_t)row * QKVN + hh * HD;               wn = qln; }
    else         { p = QKV + (size_t)row * QKVN + 768 + (hh - NH) * HD;  wn = kln; }
    float a = p[l], b = p[l + 32];
    float ss = a * a + b * b;
    #pragma unroll
    for (int o = 16; o; o >>= 1) ss += __shfl_xor_sync(~0u, ss, o);
    float r = rsqrtf(ss * (1.0f / HD) + 1e-6f);
    a *= r * wn[l];
    b *= r * wn[l + 32];
    float inv = powf(10000.0f, -((float)l) / 32.0f);
    float ang = (float)s * inv;
    float cs = cosf(ang), sn = sinf(ang);
    p[l]      = a * cs - b * sn;
    p[l + 32] = b * cs + a * sn;
}

// ---------------- causal attention (one warp per query row) on fused QKV ----------------
__global__ void attn_kernel(const float* __restrict__ QKV,
                            __nv_bfloat16* __restrict__ Oh, __nv_bfloat16* __restrict__ Ol) {
    __shared__ float qs[8][HD];
    __shared__ float sc[8][SEQ];
    int w = threadIdx.x >> 5, l = threadIdx.x & 31;
    int g = blockIdx.x * 8 + w;
    int s = g & (SEQ - 1);
    int bh = g >> 10;
    int h = bh % NH, b = bh / NH;
    int kvh = h / (NH / NKV);
    const float* qp = QKV + (size_t)(b * SEQ + s) * QKVN + h * HD;
    qs[w][l] = qp[l]; qs[w][l + 32] = qp[l + 32];
    __syncwarp();
    const float* Kb = QKV + (size_t)b * SEQ * QKVN + 768 + kvh * HD;
    const float* Vb = QKV + (size_t)b * SEQ * QKVN + 1024 + kvh * HD;
    for (int j = l; j <= s; j += 32) {
        const float4* kp = (const float4*)(Kb + (size_t)j * QKVN);
        float d = 0.f;
        #pragma unroll
        for (int i = 0; i < 16; i++) {
            float4 kk = kp[i];
            d += qs[w][4*i] * kk.x + qs[w][4*i+1] * kk.y + qs[w][4*i+2] * kk.z + qs[w][4*i+3] * kk.w;
        }
        sc[w][j] = d * 0.125f;
    }
    __syncwarp();
    float m = -1e30f;
    for (int j = l; j <= s; j += 32) m = fmaxf(m, sc[w][j]);
    #pragma unroll
    for (int o = 16; o; o >>= 1) m = fmaxf(m, __shfl_xor_sync(~0u, m, o));
    float sum = 0.f;
    for (int j = l; j <= s; j += 32) { float p = expf(sc[w][j] - m); sc[w][j] = p; sum += p; }
    #pragma unroll
    for (int o = 16; o; o >>= 1) sum += __shfl_xor_sync(~0u, sum, o);
    __syncwarp();
    float oa = 0.f, ob = 0.f;
    int j = 0;
    for (; j + 4 <= s + 1; j += 4) {
        #pragma unroll
        for (int u = 0; u < 4; u++) {
            float p = sc[w][j + u];
            const float* vp = Vb + (size_t)(j + u) * QKVN;
            oa += p * vp[l]; ob += p * vp[l + 32];
        }
    }
    for (; j <= s; j++) {
        float p = sc[w][j];
        const float* vp = Vb + (size_t)j * QKVN;
        oa += p * vp[l]; ob += p * vp[l + 32];
    }
    float invs = 1.0f / sum;
    size_t op = ((size_t)(b * SEQ + s) * NH + h) * HD;
    split1(oa * invs, &Oh[op + l], &Ol[op + l]);
    split1(ob * invs, &Oh[op + l + 32], &Ol[op + l + 32]);
}

// ---------------- causal depthwise conv -> bf16 hi/lo ----------------
__global__ void conv_split_kernel(const float* __restrict__ T, const float* __restrict__ W4,
                                  const float* __restrict__ cb,
                                  __nv_bfloat16* __restrict__ Yh, __nv_bfloat16* __restrict__ Yl) {
    int idx = blockIdx.x * blockDim.x + threadIdx.x;
    int c = idx % Hdim;
    int row = idx / Hdim;
    int s = row & (SEQ - 1);
    int b = row / SEQ;
    const float* w = W4 + (size_t)c * KCONV;
    float acc = cb[c];
    #pragma unroll
    for (int j = 0; j < KCONV; j++) {
        int sp = s - (KCONV - 1) + j;
        if (sp >= 0) {
            const float* tr = T + (size_t)(b * SEQ + sp) * H3;
            acc += w[j] * tr[c] * tr[2 * Hdim + c];
        }
    }
    float Cg = T[(size_t)row * H3 + Hdim + c];
    split1(Cg * acc, &Yh[(size_t)row * Hdim + c], &Yl[(size_t)row * Hdim + c]);
}

// ---------------- silu(gate)*up from fused [gate|up] buffer -> bf16 hi/lo ----------------
__global__ void silu_mul_split_kernel(const float* __restrict__ T,
                                      __nv_bfloat16* __restrict__ Hh, __nv_bfloat16* __restrict__ Hl) {
    int idx = blockIdx.x * blockDim.x + threadIdx.x;   // ROWS*IM
    int row = idx / IM, c = idx - row * IM;
    float g = T[(size_t)row * GUN + c];
    float u = T[(size_t)row * GUN + IM + c];
    float y = (g / (1.0f + expf(-g))) * u;
    split1(y, &Hh[idx], &Hl[idx]);
}

// ---------------- host-side plumbing ----------------
static void gemm(const __nv_bfloat16* Ah, const __nv_bfloat16* Al,
                 const __nv_bfloat16* Bh, const __nv_bfloat16* Bl,
                 float* C, int M, int N, int K, const float* bias, const float* res) {
    dim3 grid(M / 128, N / 128);
    gemm_ms<<<grid, 256, GSMEM>>>(Ah, Al, Bh, Bl, C, M, N, K, bias, res);
}

static void wsplit(const float* src, __nv_bfloat16* H, __nv_bfloat16* L, size_t n) {
    wsplit_kernel<<<(unsigned)(n / 1024), 256>>>((const float4*)src, H, L);
}

extern "C" void kernel_launch(void* const* d_in, const int* in_sizes, int n_in,
                              void* d_out, int out_size) {
    const int*   tokens  = (const int*)  d_in[0];
    const float* embed   = (const float*)d_in[1];
    const float* qw      = (const float*)d_in[2];
    const float* kw      = (const float*)d_in[3];
    const float* vw      = (const float*)d_in[4];
    const float* ow      = (const float*)d_in[5];
    const float* qln     = (const float*)d_in[6];
    const float* kln     = (const float*)d_in[7];
    const float* a_gate  = (const float*)d_in[8];
    const float* a_up    = (const float*)d_in[9];
    const float* a_down  = (const float*)d_in[10];
    const float* a_ln1   = (const float*)d_in[11];
    const float* a_ln2   = (const float*)d_in[12];
    const float* conv_w  = (const float*)d_in[13];
    const float* conv_b  = (const float*)d_in[14];
    const float* in_w    = (const float*)d_in[15];
    const float* in_b    = (const float*)d_in[16];
    const float* out_w   = (const float*)d_in[17];
    const float* out_b   = (const float*)d_in[18];
    const float* c_gate  = (const float*)d_in[19];
    const float* c_up    = (const float*)d_in[20];
    const float* c_down  = (const float*)d_in[21];
    const float* c_ln1   = (const float*)d_in[22];
    const float* c_ln2   = (const float*)d_in[23];
    const float* finln   = (const float*)d_in[24];
    const float* lm_head = (const float*)d_in[25];

    cudaFuncSetAttribute(gemm_ms, cudaFuncAttributeMaxDynamicSharedMemorySize, GSMEM);

    float *x, *qkv, *t1, *t12;
    __nv_bfloat16 *ah, *al, *wh, *wl;
    cudaGetSymbolAddress((void**)&x,   g_x);
    cudaGetSymbolAddress((void**)&qkv, g_qkv);
    cudaGetSymbolAddress((void**)&t1,  g_t1);
    cudaGetSymbolAddress((void**)&t12, g_t12);
    cudaGetSymbolAddress((void**)&ah,  g_ah);
    cudaGetSymbolAddress((void**)&al,  g_al);
    cudaGetSymbolAddress((void**)&wh,  g_wh);
    cudaGetSymbolAddress((void**)&wl,  g_wl);

    // ---- pack + split weights ----
    for (int ai = 0; ai < 4; ai++) {
        size_t d = OFF_QKV + (size_t)ai * QKVN * Hdim;
        wsplit(qw + (size_t)ai * 589824, wh + d,          wl + d,          589824);
        wsplit(kw + (size_t)ai * 196608, wh + d + 589824, wl + d + 589824, 196608);
        wsplit(vw + (size_t)ai * 196608, wh + d + 786432, wl + d + 786432, 196608);
        size_t dg = OFF_AGU + (size_t)ai * GUN * Hdim;
        wsplit(a_gate + (size_t)ai * 2359296, wh + dg,           wl + dg,           2359296);
        wsplit(a_up   + (size_t)ai * 2359296, wh + dg + 2359296, wl + dg + 2359296, 2359296);
    }
    for (int ci = 0; ci < 8; ci++) {
        size_t dg = OFF_CGU + (size_t)ci * GUN * Hdim;
        wsplit(c_gate + (size_t)ci * 2359296, wh + dg,           wl + dg,           2359296);
        wsplit(c_up   + (size_t)ci * 2359296, wh + dg + 2359296, wl + dg + 2359296, 2359296);
    }
    wsplit(ow,      wh + OFF_OW,   wl + OFF_OW,   2359296ull);
    wsplit(a_down,  wh + OFF_AD,   wl + OFF_AD,   9437184ull);
    wsplit(in_w,    wh + OFF_INW,  wl + OFF_INW,  14155776ull);
    wsplit(out_w,   wh + OFF_OUTW, wl + OFF_OUTW, 4718592ull);
    wsplit(c_down,  wh + OFF_CD,   wl + OFF_CD,   18874368ull);
    wsplit(lm_head, wh + OFF_LM,   wl + OFF_LM,   38633472ull);

    embed_kernel<<<ROWS, 256>>>(tokens, embed, x);

    int ai = 0, ci = 0;
    for (int l = 0; l < 12; l++) {
        bool full = (l == 2 || l == 5 || l == 8 || l == 11);
        if (full) {
            size_t oqkv = OFF_QKV + (size_t)ai * QKVN * Hdim;
            size_t oo   = OFF_OW  + (size_t)ai * Hdim * Hdim;
            size_t ogu  = OFF_AGU + (size_t)ai * GUN * Hdim;
            size_t od   = OFF_AD  + (size_t)ai * Hdim * IM;
            rmsnorm_split_kernel<<<ROWS, 256>>>(x, a_ln1 + (size_t)ai * Hdim, ah, al, Hdim);
            gemm(ah, al, wh + oqkv, wl + oqkv, qkv, ROWS, QKVN, Hdim, 0, 0);
            qknorm_rope_kernel<<<ROWS * 16 / 8, 256>>>(qkv, qln + (size_t)ai * HD, kln + (size_t)ai * HD);
            attn_kernel<<<BATCH * NH * SEQ / 8, 256>>>(qkv, ah, al);
            gemm(ah, al, wh + oo, wl + oo, x, ROWS, Hdim, Hdim, 0, x);
            rmsnorm_split_kernel<<<ROWS, 256>>>(x, a_ln2 + (size_t)ai * Hdim, ah, al, Hdim);
            gemm(ah, al, wh + ogu, wl + ogu, t12, ROWS, GUN, Hdim, 0, 0);
            silu_mul_split_kernel<<<(ROWS * IM) / 256, 256>>>(t12, ah, al);
            gemm(ah, al, wh + od, wl + od, x, ROWS, Hdim, IM, 0, x);
            ai++;
        } else {
            size_t oi  = OFF_INW  + (size_t)ci * H3 * Hdim;
            size_t oo  = OFF_OUTW + (size_t)ci * Hdim * Hdim;
            size_t ogu = OFF_CGU  + (size_t)ci * GUN * Hdim;
            size_t od  = OFF_CD   + (size_t)ci * Hdim * IM;
            rmsnorm_split_kernel<<<ROWS, 256>>>(x, c_ln1 + (size_t)ci * Hdim, ah, al, Hdim);
            gemm(ah, al, wh + oi, wl + oi, t1, ROWS, H3, Hdim, in_b + (size_t)ci * H3, 0);
            conv_split_kernel<<<(ROWS * Hdim) / 256, 256>>>(t1, conv_w + (size_t)ci * Hdim * KCONV,
                                                            conv_b + (size_t)ci * Hdim, ah, al);
            gemm(ah, al, wh + oo, wl + oo, x, ROWS, Hdim, Hdim, out_b + (size_t)ci * Hdim, x);
            rmsnorm_split_kernel<<<ROWS, 256>>>(x, c_ln2 + (size_t)ci * Hdim, ah, al, Hdim);
            gemm(ah, al, wh + ogu, wl + ogu, t12, ROWS, GUN, Hdim, 0, 0);
            silu_mul_split_kernel<<<(ROWS * IM) / 256, 256>>>(t12, ah, al);
            gemm(ah, al, wh + od, wl + od, x, ROWS, Hdim, IM, 0, x);
            ci++;
        }
    }
    rmsnorm_split_kernel<<<ROWS, 256>>>(x, finln, ah, al, Hdim);
    gemm(ah, al, wh + OFF_LM, wl + OFF_LM, (float*)d_out, ROWS, VOCAB, Hdim, 0, 0);
}

// round 8
// speedup vs baseline: 1.7267x; 1.7267x over previous
#include <cuda_runtime.h>
#include <cuda_bf16.h>
#include <math.h>
#include <stdint.h>

// ---------------- constants ----------------
#define Hdim 768
#define NH 12
#define NKV 4
#define HD 64
#define IM 3072
#define KCONV 4
#define SEQ 1024
#define BATCH 2
#define ROWS (BATCH*SEQ)      // 2048
#define VOCAB 50304
#define H3 (3*Hdim)           // 2304
#define QKVN 1280             // 768 + 256 + 256
#define GUN  (2*IM)           // 6144

// gemm tiling (R2-proven)
#define BK 32
#define SSTR 40                       // padded row stride (bf16) -> conflict-free ldmatrix
#define ARR_BYTES (128*SSTR*2)        // 10240
#define STAGE_BYTES (4*ARR_BYTES)     // 40960
#define SMEM_TOTAL (2*STAGE_BYTES)    // 81920

// ---------------- packed weight offsets (elems) ----------------
#define OFF_QKV  0ull                  // [4][1280][768]
#define OFF_OW   3932160ull            // [4][768][768]
#define OFF_AGU  6291456ull            // [4][6144][768]
#define OFF_AD   25165824ull           // [4][768][3072]
#define OFF_INW  34603008ull           // [8][2304][768]
#define OFF_OUTW 48758784ull           // [8][768][768]
#define OFF_CGU  53477376ull           // [8][6144][768]
#define OFF_CD   91226112ull           // [8][768][3072]
#define OFF_LM   110100480ull          // [50304][768]
#define W_TOTAL  148733952ull

// ---------------- scratch (device globals; no allocation) ----------------
__device__ float g_x  [ROWS*Hdim];
__device__ float g_qkv[ROWS*QKVN];
__device__ float g_t1 [ROWS*H3];
__device__ float g_t12[ROWS*GUN];
__device__ __nv_bfloat16 g_ah[ROWS*IM];
__device__ __nv_bfloat16 g_al[ROWS*IM];
__device__ __nv_bfloat16 g_wh[W_TOTAL];
__device__ __nv_bfloat16 g_wl[W_TOTAL];

// ---------------- helpers ----------------
__device__ __forceinline__ void split1(float x, __nv_bfloat16* h, __nv_bfloat16* l) {
    __nv_bfloat16 hh = __float2bfloat16(x);
    *h = hh;
    *l = __float2bfloat16(x - __bfloat162float(hh));
}
__device__ __forceinline__ unsigned cvta_s(const void* p) {
    return (unsigned)__cvta_generic_to_shared(p);
}
__device__ __forceinline__ void cp16(unsigned saddr, const void* g) {
    asm volatile("cp.async.cg.shared.global [%0], [%1], 16;\n" :: "r"(saddr), "l"(g));
}
__device__ __forceinline__ void ldm4(unsigned* r, unsigned addr) {
    asm volatile("ldmatrix.sync.aligned.m8n8.x4.shared.b16 {%0,%1,%2,%3}, [%4];\n"
                 : "=r"(r[0]), "=r"(r[1]), "=r"(r[2]), "=r"(r[3]) : "r"(addr));
}
__device__ __forceinline__ void mma16816(float* d, const unsigned* a, const unsigned* b) {
    asm volatile("mma.sync.aligned.m16n8k16.row.col.f32.bf16.bf16.f32 "
                 "{%0,%1,%2,%3}, {%4,%5,%6,%7}, {%8,%9}, {%0,%1,%2,%3};\n"
                 : "+f"(d[0]), "+f"(d[1]), "+f"(d[2]), "+f"(d[3])
                 : "r"(a[0]), "r"(a[1]), "r"(a[2]), "r"(a[3]), "r"(b[0]), "r"(b[1]));
}

// ================= R2-proven bf16x3 split GEMM =================
// C[M,N] = A*B^T (+bias)(+res). A,B as (hi,lo) bf16, K-major.
// Tile 128x128x32, 2-stage cp.async. grid = (N/128, M/128).
__global__ void __launch_bounds__(256) gemm_bf16x3(
    const __nv_bfloat16* __restrict__ Ah, const __nv_bfloat16* __restrict__ Al,
    const __nv_bfloat16* __restrict__ Bh, const __nv_bfloat16* __restrict__ Bl,
    float* __restrict__ C, int M, int N, int K,
    const float* __restrict__ bias, const float* __restrict__ res)
{
    extern __shared__ __align__(16) char sm_raw[];
    const int tid = threadIdx.x;
    const int lane = tid & 31, wid = tid >> 5;
    const int wm = wid >> 1, wn = wid & 1;
    const int bm = blockIdx.y * 128, bn = blockIdx.x * 128;
    const unsigned sbase = cvta_s(sm_raw);

    const int c4 = tid & 3;
    const int r0 = tid >> 2;     // 0..63

    const __nv_bfloat16* gA0 = Ah + (size_t)bm * K;
    const __nv_bfloat16* gA1 = Al + (size_t)bm * K;
    const __nv_bfloat16* gB0 = Bh + (size_t)bn * K;
    const __nv_bfloat16* gB1 = Bl + (size_t)bn * K;

    float acc[2][8][4];
    #pragma unroll
    for (int t = 0; t < 2; t++)
        #pragma unroll
        for (int n = 0; n < 8; n++)
            #pragma unroll
            for (int i = 0; i < 4; i++) acc[t][n][i] = 0.f;

    auto load_stage = [&](int st, int kt) {
        int gk = kt * BK + c4 * 8;
        unsigned s0 = sbase + st * STAGE_BYTES + (unsigned)(r0 * SSTR + c4 * 8) * 2;
        cp16(s0 + 0 * ARR_BYTES,                  gA0 + (size_t)r0 * K + gk);
        cp16(s0 + 0 * ARR_BYTES + 64 * SSTR * 2,  gA0 + (size_t)(r0 + 64) * K + gk);
        cp16(s0 + 1 * ARR_BYTES,                  gA1 + (size_t)r0 * K + gk);
        cp16(s0 + 1 * ARR_BYTES + 64 * SSTR * 2,  gA1 + (size_t)(r0 + 64) * K + gk);
        cp16(s0 + 2 * ARR_BYTES,                  gB0 + (size_t)r0 * K + gk);
        cp16(s0 + 2 * ARR_BYTES + 64 * SSTR * 2,  gB0 + (size_t)(r0 + 64) * K + gk);
        cp16(s0 + 3 * ARR_BYTES,                  gB1 + (size_t)r0 * K + gk);
        cp16(s0 + 3 * ARR_BYTES + 64 * SSTR * 2,  gB1 + (size_t)(r0 + 64) * K + gk);
    };

    const int KT = K / BK;
    load_stage(0, 0);
    asm volatile("cp.async.commit_group;\n");
    for (int kt = 0; kt < KT; kt++) {
        if (kt + 1 < KT) {
            load_stage((kt + 1) & 1, kt + 1);
            asm volatile("cp.async.commit_group;\n");
            asm volatile("cp.async.wait_group 1;\n");
        } else {
            asm volatile("cp.async.wait_group 0;\n");
        }
        __syncthreads();
        unsigned st = sbase + (kt & 1) * STAGE_BYTES;
        #pragma unroll
        for (int kk = 0; kk < BK; kk += 16) {
            unsigned ah[2][4], al[2][4], bh[8][2], bl[8][2];
            #pragma unroll
            for (int t = 0; t < 2; t++) {
                int row = wm * 32 + t * 16 + (lane & 15);
                int col = kk + ((lane >> 4) << 3);
                unsigned off = (unsigned)(row * SSTR + col) * 2;
                ldm4(ah[t], st + off);
                ldm4(al[t], st + ARR_BYTES + off);
            }
            #pragma unroll
            for (int p = 0; p < 4; p++) {
                int m = lane >> 3;
                int row = wn * 64 + p * 16 + ((m >> 1) << 3) + (lane & 7);
                int col = kk + ((m & 1) << 3);
                unsigned off = (unsigned)(row * SSTR + col) * 2;
                unsigned r[4];
                ldm4(r, st + 2 * ARR_BYTES + off);
                bh[2 * p][0] = r[0]; bh[2 * p][1] = r[1];
                bh[2 * p + 1][0] = r[2]; bh[2 * p + 1][1] = r[3];
                ldm4(r, st + 3 * ARR_BYTES + off);
                bl[2 * p][0] = r[0]; bl[2 * p][1] = r[1];
                bl[2 * p + 1][0] = r[2]; bl[2 * p + 1][1] = r[3];
            }
            #pragma unroll
            for (int t = 0; t < 2; t++)
                #pragma unroll
                for (int n = 0; n < 8; n++) {
                    mma16816(acc[t][n], ah[t], bh[n]);
                    mma16816(acc[t][n], ah[t], bl[n]);
                    mma16816(acc[t][n], al[t], bh[n]);
                }
        }
        __syncthreads();
    }

    // epilogue (R2-proven)
    #pragma unroll
    for (int t = 0; t < 2; t++) {
        int row0 = bm + wm * 32 + t * 16 + (lane >> 2);
        #pragma unroll
        for (int n = 0; n < 8; n++) {
            int col = bn + wn * 64 + n * 8 + (lane & 3) * 2;
            #pragma unroll
            for (int hh = 0; hh < 2; hh++) {
                int row = row0 + hh * 8;
                float v0 = acc[t][n][hh * 2], v1 = acc[t][n][hh * 2 + 1];
                if (bias) { v0 += bias[col]; v1 += bias[col + 1]; }
                if (res) {
                    const float* rp = res + (size_t)row * N + col;
                    v0 += rp[0]; v1 += rp[1];
                }
                *(float2*)(C + (size_t)row * N + col) = make_float2(v0, v1);
            }
        }
    }
}

// ---------------- single fused weight-split kernel ----------------
#define NSEG 42
struct WSeg { const float4* src; long long dst4; long long end4; };
struct WPlan { WSeg s[NSEG]; };

__global__ void wsplit_all_kernel(WPlan p, __nv_bfloat16* __restrict__ H,
                                  __nv_bfloat16* __restrict__ L, long long total4) {
    long long idx = (long long)blockIdx.x * 256 + threadIdx.x;
    if (idx >= total4) return;
    int lo = 0, hi = NSEG - 1;
    while (lo < hi) { int mid = (lo + hi) >> 1; if (idx < p.s[mid].end4) hi = mid; else lo = mid + 1; }
    long long start = lo ? p.s[lo - 1].end4 : 0;
    long long off = idx - start;
    float4 v = p.s[lo].src[off];
    long long d = p.s[lo].dst4 + off;
    __nv_bfloat16 h[4], l[4];
    split1(v.x, &h[0], &l[0]); split1(v.y, &h[1], &l[1]);
    split1(v.z, &h[2], &l[2]); split1(v.w, &h[3], &l[3]);
    ((__nv_bfloat162*)H)[d * 2]     = *(__nv_bfloat162*)&h[0];
    ((__nv_bfloat162*)H)[d * 2 + 1] = *(__nv_bfloat162*)&h[2];
    ((__nv_bfloat162*)L)[d * 2]     = *(__nv_bfloat162*)&l[0];
    ((__nv_bfloat162*)L)[d * 2 + 1] = *(__nv_bfloat162*)&l[2];
}

// ---------------- embedding gather ----------------
__global__ void embed_kernel(const int* __restrict__ tok, const float* __restrict__ E,
                             float* __restrict__ X) {
    int row = blockIdx.x;
    int t = tok[row];
    const float* src = E + (size_t)t * Hdim;
    float* dst = X + (size_t)row * Hdim;
    for (int c = threadIdx.x; c < Hdim; c += blockDim.x) dst[c] = src[c];
}

// ---------------- rmsnorm -> bf16 hi/lo ----------------
__global__ void rmsnorm_split_kernel(const float* __restrict__ X, const float* __restrict__ W,
                                     __nv_bfloat16* __restrict__ Hh, __nv_bfloat16* __restrict__ Hl,
                                     int n) {
    int row = blockIdx.x;
    const float* x = X + (size_t)row * n;
    float s = 0.f;
    for (int c = threadIdx.x; c < n; c += blockDim.x) { float v = x[c]; s += v * v; }
    __shared__ float sm[32];
    #pragma unroll
    for (int o = 16; o; o >>= 1) s += __shfl_xor_sync(~0u, s, o);
    if ((threadIdx.x & 31) == 0) sm[threadIdx.x >> 5] = s;
    __syncthreads();
    if (threadIdx.x < 32) {
        float v = (threadIdx.x < (blockDim.x >> 5)) ? sm[threadIdx.x] : 0.f;
        #pragma unroll
        for (int o = 4; o; o >>= 1) v += __shfl_xor_sync(~0u, v, o);
        if (threadIdx.x == 0) sm[0] = v;
    }
    __syncthreads();
    float r = rsqrtf(sm[0] / (float)n + 1e-6f);
    for (int c = threadIdx.x; c < n; c += blockDim.x) {
        float y = x[c] * r * W[c];
        split1(y, &Hh[(size_t)row * n + c], &Hl[(size_t)row * n + c]);
    }
}

// ---------------- per-head RMSNorm (q/k) + RoPE on fused QKV buffer ----------------
__global__ void qknorm_rope_kernel(float* __restrict__ QKV,
                                   const float* __restrict__ qln, const float* __restrict__ kln) {
    int w = threadIdx.x >> 5, l = threadIdx.x & 31;
    int g = blockIdx.x * 8 + w;
    int hh = g & 15;
    int row = g >> 4;
    int s = row & (SEQ - 1);
    float* p; const float* wn;
    if (hh < NH) { p = QKV + (size_t)row * QKVN + hh * HD;               wn = qln; }
    else         { p = QKV + (size_t)row * QKVN + 768 + (hh - NH) * HD;  wn = kln; }
    float a = p[l], b = p[l + 32];
    float ss = a * a + b * b;
    #pragma unroll
    for (int o = 16; o; o >>= 1) ss += __shfl_xor_sync(~0u, ss, o);
    float r = rsqrtf(ss * (1.0f / HD) + 1e-6f);
    a *= r * wn[l];
    b *= r * wn[l + 32];
    float inv = powf(10000.0f, -((float)l) / 32.0f);
    float ang = (float)s * inv;
    float cs = cosf(ang), sn = sinf(ang);
    p[l]      = a * cs - b * sn;
    p[l + 32] = b * cs + a * sn;
}

// ---------------- causal attention (one warp per query row) on fused QKV ----------------
__global__ void attn_kernel(const float* __restrict__ QKV,
                            __nv_bfloat16* __restrict__ Oh, __nv_bfloat16* __restrict__ Ol) {
    __shared__ float qs[8][HD];
    __shared__ float sc[8][SEQ];
    int w = threadIdx.x >> 5, l = threadIdx.x & 31;
    int g = blockIdx.x * 8 + w;
    int s = g & (SEQ - 1);
    int bh = g >> 10;
    int h = bh % NH, b = bh / NH;
    int kvh = h / (NH / NKV);
    const float* qp = QKV + (size_t)(b * SEQ + s) * QKVN + h * HD;
    qs[w][l] = qp[l]; qs[w][l + 32] = qp[l + 32];
    __syncwarp();
    const float* Kb = QKV + (size_t)b * SEQ * QKVN + 768 + kvh * HD;
    const float* Vb = QKV + (size_t)b * SEQ * QKVN + 1024 + kvh * HD;
    for (int j = l; j <= s; j += 32) {
        const float4* kp = (const float4*)(Kb + (size_t)j * QKVN);
        float d = 0.f;
        #pragma unroll
        for (int i = 0; i < 16; i++) {
            float4 kk = kp[i];
            d += qs[w][4*i] * kk.x + qs[w][4*i+1] * kk.y + qs[w][4*i+2] * kk.z + qs[w][4*i+3] * kk.w;
        }
        sc[w][j] = d * 0.125f;
    }
    __syncwarp();
    float m = -1e30f;
    for (int j = l; j <= s; j += 32) m = fmaxf(m, sc[w][j]);
    #pragma unroll
    for (int o = 16; o; o >>= 1) m = fmaxf(m, __shfl_xor_sync(~0u, m, o));
    float sum = 0.f;
    for (int j = l; j <= s; j += 32) { float p = expf(sc[w][j] - m); sc[w][j] = p; sum += p; }
    #pragma unroll
    for (int o = 16; o; o >>= 1) sum += __shfl_xor_sync(~0u, sum, o);
    __syncwarp();
    float oa = 0.f, ob = 0.f;
    int j = 0;
    for (; j + 4 <= s + 1; j += 4) {
        #pragma unroll
        for (int u = 0; u < 4; u++) {
            float p = sc[w][j + u];
            const float* vp = Vb + (size_t)(j + u) * QKVN;
            oa += p * vp[l]; ob += p * vp[l + 32];
        }
    }
    for (; j <= s; j++) {
        float p = sc[w][j];
        const float* vp = Vb + (size_t)j * QKVN;
        oa += p * vp[l]; ob += p * vp[l + 32];
    }
    float invs = 1.0f / sum;
    size_t op = ((size_t)(b * SEQ + s) * NH + h) * HD;
    split1(oa * invs, &Oh[op + l], &Ol[op + l]);
    split1(ob * invs, &Oh[op + l + 32], &Ol[op + l + 32]);
}

// ---------------- causal depthwise conv -> bf16 hi/lo ----------------
__global__ void conv_split_kernel(const float* __restrict__ T, const float* __restrict__ W4,
                                  const float* __restrict__ cb,
                                  __nv_bfloat16* __restrict__ Yh, __nv_bfloat16* __restrict__ Yl) {
    int idx = blockIdx.x * blockDim.x + threadIdx.x;
    int c = idx % Hdim;
    int row = idx / Hdim;
    int s = row & (SEQ - 1);
    int b = row / SEQ;
    const float* w = W4 + (size_t)c * KCONV;
    float acc = cb[c];
    #pragma unroll
    for (int j = 0; j < KCONV; j++) {
        int sp = s - (KCONV - 1) + j;
        if (sp >= 0) {
            const float* tr = T + (size_t)(b * SEQ + sp) * H3;
            acc += w[j] * tr[c] * tr[2 * Hdim + c];
        }
    }
    float Cg = T[(size_t)row * H3 + Hdim + c];
    split1(Cg * acc, &Yh[(size_t)row * Hdim + c], &Yl[(size_t)row * Hdim + c]);
}

// ---------------- silu(gate)*up from fused [gate|up] buffer -> bf16 hi/lo ----------------
__global__ void silu_mul_split_kernel(const float* __restrict__ T,
                                      __nv_bfloat16* __restrict__ Hh, __nv_bfloat16* __restrict__ Hl) {
    int idx = blockIdx.x * blockDim.x + threadIdx.x;   // ROWS*IM
    int row = idx / IM, c = idx - row * IM;
    float g = T[(size_t)row * GUN + c];
    float u = T[(size_t)row * GUN + IM + c];
    float y = (g / (1.0f + expf(-g))) * u;
    split1(y, &Hh[idx], &Hl[idx]);
}

// ---------------- host-side plumbing ----------------
static void gemm(const __nv_bfloat16* Ah, const __nv_bfloat16* Al,
                 const __nv_bfloat16* Bh, const __nv_bfloat16* Bl,
                 float* C, int M, int N, int K, const float* bias, const float* res) {
    dim3 grid(N / 128, M / 128);
    gemm_bf16x3<<<grid, 256, SMEM_TOTAL>>>(Ah, Al, Bh, Bl, C, M, N, K, bias, res);
}

extern "C" void kernel_launch(void* const* d_in, const int* in_sizes, int n_in,
                              void* d_out, int out_size) {
    const int*   tokens  = (const int*)  d_in[0];
    const float* embed   = (const float*)d_in[1];
    const float* qw      = (const float*)d_in[2];
    const float* kw      = (const float*)d_in[3];
    const float* vw      = (const float*)d_in[4];
    const float* ow      = (const float*)d_in[5];
    const float* qln     = (const float*)d_in[6];
    const float* kln     = (const float*)d_in[7];
    const float* a_gate  = (const float*)d_in[8];
    const float* a_up    = (const float*)d_in[9];
    const float* a_down  = (const float*)d_in[10];
    const float* a_ln1   = (const float*)d_in[11];
    const float* a_ln2   = (const float*)d_in[12];
    const float* conv_w  = (const float*)d_in[13];
    const float* conv_b  = (const float*)d_in[14];
    const float* in_w    = (const float*)d_in[15];
    const float* in_b    = (const float*)d_in[16];
    const float* out_w   = (const float*)d_in[17];
    const float* out_b   = (const float*)d_in[18];
    const float* c_gate  = (const float*)d_in[19];
    const float* c_up    = (const float*)d_in[20];
    const float* c_down  = (const float*)d_in[21];
    const float* c_ln1   = (const float*)d_in[22];
    const float* c_ln2   = (const float*)d_in[23];
    const float* finln   = (const float*)d_in[24];
    const float* lm_head = (const float*)d_in[25];

    cudaFuncSetAttribute(gemm_bf16x3, cudaFuncAttributeMaxDynamicSharedMemorySize, SMEM_TOTAL);

    float *x, *qkv, *t1, *t12;
    __nv_bfloat16 *ah, *al, *wh, *wl;
    cudaGetSymbolAddress((void**)&x,   g_x);
    cudaGetSymbolAddress((void**)&qkv, g_qkv);
    cudaGetSymbolAddress((void**)&t1,  g_t1);
    cudaGetSymbolAddress((void**)&t12, g_t12);
    cudaGetSymbolAddress((void**)&ah,  g_ah);
    cudaGetSymbolAddress((void**)&al,  g_al);
    cudaGetSymbolAddress((void**)&wh,  g_wh);
    cudaGetSymbolAddress((void**)&wl,  g_wl);

    // ---- build the single weight-split plan (42 segments) ----
    WPlan plan;
    long long cum = 0;
    int si = 0;
    auto seg = [&](const float* src, unsigned long long dst_elems, long long n_elems) {
        plan.s[si].src  = (const float4*)src;
        plan.s[si].dst4 = (long long)(dst_elems / 4);
        cum += n_elems / 4;
        plan.s[si].end4 = cum;
        si++;
    };
    for (int ai = 0; ai < 4; ai++) {
        unsigned long long d = OFF_QKV + (unsigned long long)ai * QKVN * Hdim;
        seg(qw + (size_t)ai * 589824, d,          589824);
        seg(kw + (size_t)ai * 196608, d + 589824, 196608);
        seg(vw + (size_t)ai * 196608, d + 786432, 196608);
    }
    seg(ow, OFF_OW, 2359296);
    for (int ai = 0; ai < 4; ai++) {
        unsigned long long d = OFF_AGU + (unsigned long long)ai * GUN * Hdim;
        seg(a_gate + (size_t)ai * 2359296, d,           2359296);
        seg(a_up   + (size_t)ai * 2359296, d + 2359296, 2359296);
    }
    seg(a_down, OFF_AD,   9437184);
    seg(in_w,   OFF_INW,  14155776);
    seg(out_w,  OFF_OUTW, 4718592);
    for (int ci = 0; ci < 8; ci++) {
        unsigned long long d = OFF_CGU + (unsigned long long)ci * GUN * Hdim;
        seg(c_gate + (size_t)ci * 2359296, d,           2359296);
        seg(c_up   + (size_t)ci * 2359296, d + 2359296, 2359296);
    }
    seg(c_down,  OFF_CD, 18874368);
    seg(lm_head, OFF_LM, 38633472);

    long long total4 = (long long)(W_TOTAL / 4);
    wsplit_all_kernel<<<(unsigned)((total4 + 255) / 256), 256>>>(plan, wh, wl, total4);

    embed_kernel<<<ROWS, 256>>>(tokens, embed, x);

    int ai = 0, ci = 0;
    for (int l = 0; l < 12; l++) {
        bool full = (l == 2 || l == 5 || l == 8 || l == 11);
        if (full) {
            size_t oqkv = OFF_QKV + (size_t)ai * QKVN * Hdim;
            size_t oo   = OFF_OW  + (size_t)ai * Hdim * Hdim;
            size_t ogu  = OFF_AGU + (size_t)ai * GUN * Hdim;
            size_t od   = OFF_AD  + (size_t)ai * Hdim * IM;
            rmsnorm_split_kernel<<<ROWS, 256>>>(x, a_ln1 + (size_t)ai * Hdim, ah, al, Hdim);
            gemm(ah, al, wh + oqkv, wl + oqkv, qkv, ROWS, QKVN, Hdim, 0, 0);
            qknorm_rope_kernel<<<ROWS * 16 / 8, 256>>>(qkv, qln + (size_t)ai * HD, kln + (size_t)ai * HD);
            attn_kernel<<<BATCH * NH * SEQ / 8, 256>>>(qkv, ah, al);
            gemm(ah, al, wh + oo, wl + oo, x, ROWS, Hdim, Hdim, 0, x);
            rmsnorm_split_kernel<<<ROWS, 256>>>(x, a_ln2 + (size_t)ai * Hdim, ah, al, Hdim);
            gemm(ah, al, wh + ogu, wl + ogu, t12, ROWS, GUN, Hdim, 0, 0);
            silu_mul_split_kernel<<<(ROWS * IM) / 256, 256>>>(t12, ah, al);
            gemm(ah, al, wh + od, wl + od, x, ROWS, Hdim, IM, 0, x);
            ai++;
        } else {
            size_t oi  = OFF_INW  + (size_t)ci * H3 * Hdim;
            size_t oo  = OFF_OUTW + (size_t)ci * Hdim * Hdim;
            size_t ogu = OFF_CGU  + (size_t)ci * GUN * Hdim;
            size_t od  = OFF_CD   + (size_t)ci * Hdim * IM;
            rmsnorm_split_kernel<<<ROWS, 256>>>(x, c_ln1 + (size_t)ci * Hdim, ah, al, Hdim);
            gemm(ah, al, wh + oi, wl + oi, t1, ROWS, H3, Hdim, in_b + (size_t)ci * H3, 0);
            conv_split_kernel<<<(ROWS * Hdim) / 256, 256>>>(t1, conv_w + (size_t)ci * Hdim * KCONV,
                                                            conv_b + (size_t)ci * Hdim, ah, al);
            gemm(ah, al, wh + oo, wl + oo, x, ROWS, Hdim, Hdim, out_b + (size_t)ci * Hdim, x);
            rmsnorm_split_kernel<<<ROWS, 256>>>(x, c_ln2 + (size_t)ci * Hdim, ah, al, Hdim);
            gemm(ah, al, wh + ogu, wl + ogu, t12, ROWS, GUN, Hdim, 0, 0);
            silu_mul_split_kernel<<<(ROWS * IM) / 256, 256>>>(t12, ah, al);
            gemm(ah, al, wh + od, wl + od, x, ROWS, Hdim, IM, 0, x);
            ci++;
        }
    }
    rmsnorm_split_kernel<<<ROWS, 256>>>(x, finln, ah, al, Hdim);
    gemm(ah, al, wh + OFF_LM, wl + OFF_LM, (float*)d_out, ROWS, VOCAB, Hdim, 0, 0);
}

// round 9
// speedup vs baseline: 1.7782x; 1.0298x over previous
#include <cuda_runtime.h>
#include <cuda_bf16.h>
#include <math.h>
#include <stdint.h>

// ---------------- constants ----------------
#define Hdim 768
#define NH 12
#define NKV 4
#define HD 64
#define IM 3072
#define KCONV 4
#define SEQ 1024
#define BATCH 2
#define ROWS (BATCH*SEQ)      // 2048
#define VOCAB 50304
#define H3 (3*Hdim)           // 2304
#define QKVN 1280             // 768 + 256 + 256
#define GUN  (2*IM)           // 6144

// gemm tiling: 128x128x32 tile, XOR-swizzled smem, 3-stage pipeline
#define BK 32
#define ARR_B 8192                    // 128 rows x 64B (32 bf16), swizzled
#define STAGE_B (4*ARR_B)             // 32768 (Ah,Al,Bh,Bl)
#define NST 3
#define SMEM_TOTAL (NST*STAGE_B)      // 98304 -> 2 CTAs/SM

// ---------------- packed weight offsets (elems) ----------------
#define OFF_QKV  0ull                  // [4][1280][768]
#define OFF_OW   3932160ull            // [4][768][768]
#define OFF_AGU  6291456ull            // [4][6144][768]
#define OFF_AD   25165824ull           // [4][768][3072]
#define OFF_INW  34603008ull           // [8][2304][768]
#define OFF_OUTW 48758784ull           // [8][768][768]
#define OFF_CGU  53477376ull           // [8][6144][768]
#define OFF_CD   91226112ull           // [8][768][3072]
#define OFF_LM   110100480ull          // [50304][768]
#define W_TOTAL  148733952ull

// ---------------- scratch (device globals; no allocation) ----------------
__device__ float g_x  [ROWS*Hdim];
__device__ float g_qkv[ROWS*QKVN];
__device__ float g_t1 [ROWS*H3];
__device__ float g_t12[ROWS*GUN];
__device__ __nv_bfloat16 g_ah[ROWS*IM];
__device__ __nv_bfloat16 g_al[ROWS*IM];
__device__ __nv_bfloat16 g_wh[W_TOTAL];
__device__ __nv_bfloat16 g_wl[W_TOTAL];

// ---------------- helpers ----------------
__device__ __forceinline__ void split1(float x, __nv_bfloat16* h, __nv_bfloat16* l) {
    __nv_bfloat16 hh = __float2bfloat16(x);
    *h = hh;
    *l = __float2bfloat16(x - __bfloat162float(hh));
}
__device__ __forceinline__ unsigned cvta_s(const void* p) {
    return (unsigned)__cvta_generic_to_shared(p);
}
__device__ __forceinline__ void cp16(unsigned saddr, const void* g) {
    asm volatile("cp.async.cg.shared.global [%0], [%1], 16;\n" :: "r"(saddr), "l"(g));
}
__device__ __forceinline__ void ldm4(unsigned* r, unsigned addr) {
    asm volatile("ldmatrix.sync.aligned.m8n8.x4.shared.b16 {%0,%1,%2,%3}, [%4];\n"
                 : "=r"(r[0]), "=r"(r[1]), "=r"(r[2]), "=r"(r[3]) : "r"(addr));
}
__device__ __forceinline__ void mma16816(float* d, const unsigned* a, const unsigned* b) {
    asm volatile("mma.sync.aligned.m16n8k16.row.col.f32.bf16.bf16.f32 "
                 "{%0,%1,%2,%3}, {%4,%5,%6,%7}, {%8,%9}, {%0,%1,%2,%3};\n"
                 : "+f"(d[0]), "+f"(d[1]), "+f"(d[2]), "+f"(d[3])
                 : "r"(a[0]), "r"(a[1]), "r"(a[2]), "r"(a[3]), "r"(b[0]), "r"(b[1]));
}
// swizzled address within one 128x32 bf16 array (64B rows):
// 16B-unit u = col/8; u' = u ^ ((row>>1)&3)  -> conflict-free ldmatrix + cp.async
__device__ __forceinline__ unsigned sw_addr(unsigned base, int row, int col) {
    int u = col >> 3;
    return base + row * 64 + ((u ^ ((row >> 1) & 3)) << 4);
}

// ================= bf16x3 split GEMM, 3-stage swizzled =================
// C[M,N] = A*B^T (+bias)(+res). A,B as (hi,lo) bf16, K-major.
// grid = (M/128, N/128)  [M fast -> B-tile L2 reuse across a wave]
__global__ void __launch_bounds__(256) gemm_bf16x3(
    const __nv_bfloat16* __restrict__ Ah, const __nv_bfloat16* __restrict__ Al,
    const __nv_bfloat16* __restrict__ Bh, const __nv_bfloat16* __restrict__ Bl,
    float* __restrict__ C, int M, int N, int K,
    const float* __restrict__ bias, const float* __restrict__ res)
{
    extern __shared__ __align__(16) char sm_raw[];
    const int tid = threadIdx.x;
    const int lane = tid & 31, wid = tid >> 5;
    const int wm = wid >> 1, wn = wid & 1;
    const int bm = blockIdx.x * 128, bn = blockIdx.y * 128;
    const unsigned sbase = cvta_s(sm_raw);

    const __nv_bfloat16* gp[4] = {
        Ah + (size_t)bm * K, Al + (size_t)bm * K,
        Bh + (size_t)bn * K, Bl + (size_t)bn * K };

    float acc[2][8][4];
    #pragma unroll
    for (int t = 0; t < 2; t++)
        #pragma unroll
        for (int n = 0; n < 8; n++)
            #pragma unroll
            for (int i = 0; i < 4; i++) acc[t][n][i] = 0.f;

    auto load_chunk = [&](int st, int c) {
        int gk = c * BK;
        unsigned sb = sbase + st * STAGE_B;
        #pragma unroll
        for (int i = 0; i < 8; i++) {
            int idx = tid + i * 256;          // 0..2047
            int arr = idx >> 9;               // 0..3
            int j = idx & 511;
            int r = j >> 2, u = j & 3;
            unsigned sa = sb + arr * ARR_B + r * 64 + ((u ^ ((r >> 1) & 3)) << 4);
            cp16(sa, gp[arr] + (size_t)r * K + gk + u * 8);
        }
        asm volatile("cp.async.commit_group;\n");
    };

    const int KT = K / BK;
    load_chunk(0, 0);
    load_chunk(1, 1);

    for (int c = 0; c < KT; c++) {
        if (c + 1 < KT) asm volatile("cp.async.wait_group 1;\n");
        else            asm volatile("cp.async.wait_group 0;\n");
        __syncthreads();
        if (c + 2 < KT) load_chunk((c + 2) % NST, c + 2);

        unsigned st = sbase + (c % NST) * STAGE_B;
        #pragma unroll
        for (int kk = 0; kk < BK; kk += 16) {
            unsigned ah[2][4], al[2][4], bh[8][2], bl[8][2];
            #pragma unroll
            for (int t = 0; t < 2; t++) {
                int row = wm * 32 + t * 16 + (lane & 15);
                int col = kk + ((lane >> 4) << 3);
                ldm4(ah[t], sw_addr(st,             row, col));
                ldm4(al[t], sw_addr(st + ARR_B,     row, col));
            }
            #pragma unroll
            for (int p = 0; p < 4; p++) {
                int m = lane >> 3;
                int row = wn * 64 + p * 16 + ((m >> 1) << 3) + (lane & 7);
                int col = kk + ((m & 1) << 3);
                unsigned r[4];
                ldm4(r, sw_addr(st + 2 * ARR_B, row, col));
                bh[2 * p][0] = r[0]; bh[2 * p][1] = r[1];
                bh[2 * p + 1][0] = r[2]; bh[2 * p + 1][1] = r[3];
                ldm4(r, sw_addr(st + 3 * ARR_B, row, col));
                bl[2 * p][0] = r[0]; bl[2 * p][1] = r[1];
                bl[2 * p + 1][0] = r[2]; bl[2 * p + 1][1] = r[3];
            }
            #pragma unroll
            for (int t = 0; t < 2; t++)
                #pragma unroll
                for (int n = 0; n < 8; n++) {
                    mma16816(acc[t][n], ah[t], bh[n]);
                    mma16816(acc[t][n], ah[t], bl[n]);
                    mma16816(acc[t][n], al[t], bh[n]);
                }
        }
    }

    // epilogue (R2/R8-proven, direct reg->global)
    #pragma unroll
    for (int t = 0; t < 2; t++) {
        int row0 = bm + wm * 32 + t * 16 + (lane >> 2);
        #pragma unroll
        for (int n = 0; n < 8; n++) {
            int col = bn + wn * 64 + n * 8 + (lane & 3) * 2;
            #pragma unroll
            for (int hh = 0; hh < 2; hh++) {
                int row = row0 + hh * 8;
                float v0 = acc[t][n][hh * 2], v1 = acc[t][n][hh * 2 + 1];
                if (bias) { v0 += bias[col]; v1 += bias[col + 1]; }
                if (res) {
                    const float* rp = res + (size_t)row * N + col;
                    v0 += rp[0]; v1 += rp[1];
                }
                *(float2*)(C + (size_t)row * N + col) = make_float2(v0, v1);
            }
        }
    }
}

// ---------------- single fused weight-split kernel ----------------
#define NSEG 42
struct WSeg { const float4* src; long long dst4; long long end4; };
struct WPlan { WSeg s[NSEG]; };

__global__ void wsplit_all_kernel(WPlan p, __nv_bfloat16* __restrict__ H,
                                  __nv_bfloat16* __restrict__ L, long long total4) {
    long long idx = (long long)blockIdx.x * 256 + threadIdx.x;
    if (idx >= total4) return;
    int lo = 0, hi = NSEG - 1;
    while (lo < hi) { int mid = (lo + hi) >> 1; if (idx < p.s[mid].end4) hi = mid; else lo = mid + 1; }
    long long start = lo ? p.s[lo - 1].end4 : 0;
    long long off = idx - start;
    float4 v = p.s[lo].src[off];
    long long d = p.s[lo].dst4 + off;
    __nv_bfloat16 h[4], l[4];
    split1(v.x, &h[0], &l[0]); split1(v.y, &h[1], &l[1]);
    split1(v.z, &h[2], &l[2]); split1(v.w, &h[3], &l[3]);
    ((__nv_bfloat162*)H)[d * 2]     = *(__nv_bfloat162*)&h[0];
    ((__nv_bfloat162*)H)[d * 2 + 1] = *(__nv_bfloat162*)&h[2];
    ((__nv_bfloat162*)L)[d * 2]     = *(__nv_bfloat162*)&l[0];
    ((__nv_bfloat162*)L)[d * 2 + 1] = *(__nv_bfloat162*)&l[2];
}

// ---------------- embedding gather ----------------
__global__ void embed_kernel(const int* __restrict__ tok, const float* __restrict__ E,
                             float* __restrict__ X) {
    int row = blockIdx.x;
    int t = tok[row];
    const float* src = E + (size_t)t * Hdim;
    float* dst = X + (size_t)row * Hdim;
    for (int c = threadIdx.x; c < Hdim; c += blockDim.x) dst[c] = src[c];
}

// ---------------- rmsnorm -> bf16 hi/lo ----------------
__global__ void rmsnorm_split_kernel(const float* __restrict__ X, const float* __restrict__ W,
                                     __nv_bfloat16* __restrict__ Hh, __nv_bfloat16* __restrict__ Hl,
                                     int n) {
    int row = blockIdx.x;
    const float* x = X + (size_t)row * n;
    float s = 0.f;
    for (int c = threadIdx.x; c < n; c += blockDim.x) { float v = x[c]; s += v * v; }
    __shared__ float sm[32];
    #pragma unroll
    for (int o = 16; o; o >>= 1) s += __shfl_xor_sync(~0u, s, o);
    if ((threadIdx.x & 31) == 0) sm[threadIdx.x >> 5] = s;
    __syncthreads();
    if (threadIdx.x < 32) {
        float v = (threadIdx.x < (blockDim.x >> 5)) ? sm[threadIdx.x] : 0.f;
        #pragma unroll
        for (int o = 4; o; o >>= 1) v += __shfl_xor_sync(~0u, v, o);
        if (threadIdx.x == 0) sm[0] = v;
    }
    __syncthreads();
    float r = rsqrtf(sm[0] / (float)n + 1e-6f);
    for (int c = threadIdx.x; c < n; c += blockDim.x) {
        float y = x[c] * r * W[c];
        split1(y, &Hh[(size_t)row * n + c], &Hl[(size_t)row * n + c]);
    }
}

// ---------------- per-head RMSNorm (q/k) + RoPE on fused QKV buffer ----------------
__global__ void qknorm_rope_kernel(float* __restrict__ QKV,
                                   const float* __restrict__ qln, const float* __restrict__ kln) {
    int w = threadIdx.x >> 5, l = threadIdx.x & 31;
    int g = blockIdx.x * 8 + w;
    int hh = g & 15;
    int row = g >> 4;
    int s = row & (SEQ - 1);
    float* p; const float* wn;
    if (hh < NH) { p = QKV + (size_t)row * QKVN + hh * HD;               wn = qln; }
    else         { p = QKV + (size_t)row * QKVN + 768 + (hh - NH) * HD;  wn = kln; }
    float a = p[l], b = p[l + 32];
    float ss = a * a + b * b;
    #pragma unroll
    for (int o = 16; o; o >>= 1) ss += __shfl_xor_sync(~0u, ss, o);
    float r = rsqrtf(ss * (1.0f / HD) + 1e-6f);
    a *= r * wn[l];
    b *= r * wn[l + 32];
    float inv = powf(10000.0f, -((float)l) / 32.0f);
    float ang = (float)s * inv;
    float cs = cosf(ang), sn = sinf(ang);
    p[l]      = a * cs - b * sn;
    p[l + 32] = b * cs + a * sn;
}

// ---------------- causal attention (one warp per query row) on fused QKV ----------------
__global__ void attn_kernel(const float* __restrict__ QKV,
                            __nv_bfloat16* __restrict__ Oh, __nv_bfloat16* __restrict__ Ol) {
    __shared__ float qs[8][HD];
    __shared__ float sc[8][SEQ];
    int w = threadIdx.x >> 5, l = threadIdx.x & 31;
    int g = blockIdx.x * 8 + w;
    int s = g & (SEQ - 1);
    int bh = g >> 10;
    int h = bh % NH, b = bh / NH;
    int kvh = h / (NH / NKV);
    const float* qp = QKV + (size_t)(b * SEQ + s) * QKVN + h * HD;
    qs[w][l] = qp[l]; qs[w][l + 32] = qp[l + 32];
    __syncwarp();
    const float* Kb = QKV + (size_t)b * SEQ * QKVN + 768 + kvh * HD;
    const float* Vb = QKV + (size_t)b * SEQ * QKVN + 1024 + kvh * HD;
    for (int j = l; j <= s; j += 32) {
        const float4* kp = (const float4*)(Kb + (size_t)j * QKVN);
        float d = 0.f;
        #pragma unroll
        for (int i = 0; i < 16; i++) {
            float4 kk = kp[i];
            d += qs[w][4*i] * kk.x + qs[w][4*i+1] * kk.y + qs[w][4*i+2] * kk.z + qs[w][4*i+3] * kk.w;
        }
        sc[w][j] = d * 0.125f;
    }
    __syncwarp();
    float m = -1e30f;
    for (int j = l; j <= s; j += 32) m = fmaxf(m, sc[w][j]);
    #pragma unroll
    for (int o = 16; o; o >>= 1) m = fmaxf(m, __shfl_xor_sync(~0u, m, o));
    float sum = 0.f;
    for (int j = l; j <= s; j += 32) { float p = expf(sc[w][j] - m); sc[w][j] = p; sum += p; }
    #pragma unroll
    for (int o = 16; o; o >>= 1) sum += __shfl_xor_sync(~0u, sum, o);
    __syncwarp();
    float oa = 0.f, ob = 0.f;
    int j = 0;
    for (; j + 4 <= s + 1; j += 4) {
        #pragma unroll
        for (int u = 0; u < 4; u++) {
            float p = sc[w][j + u];
            const float* vp = Vb + (size_t)(j + u) * QKVN;
            oa += p * vp[l]; ob += p * vp[l + 32];
        }
    }
    for (; j <= s; j++) {
        float p = sc[w][j];
        const float* vp = Vb + (size_t)j * QKVN;
        oa += p * vp[l]; ob += p * vp[l + 32];
    }
    float invs = 1.0f / sum;
    size_t op = ((size_t)(b * SEQ + s) * NH + h) * HD;
    split1(oa * invs, &Oh[op + l], &Ol[op + l]);
    split1(ob * invs, &Oh[op + l + 32], &Ol[op + l + 32]);
}

// ---------------- causal depthwise conv -> bf16 hi/lo ----------------
__global__ void conv_split_kernel(const float* __restrict__ T, const float* __restrict__ W4,
                                  const float* __restrict__ cb,
                                  __nv_bfloat16* __restrict__ Yh, __nv_bfloat16* __restrict__ Yl) {
    int idx = blockIdx.x * blockDim.x + threadIdx.x;
    int c = idx % Hdim;
    int row = idx / Hdim;
    int s = row & (SEQ - 1);
    int b = row / SEQ;
    const float* w = W4 + (size_t)c * KCONV;
    float acc = cb[c];
    #pragma unroll
    for (int j = 0; j < KCONV; j++) {
        int sp = s - (KCONV - 1) + j;
        if (sp >= 0) {
            const float* tr = T + (size_t)(b * SEQ + sp) * H3;
            acc += w[j] * tr[c] * tr[2 * Hdim + c];
        }
    }
    float Cg = T[(size_t)row * H3 + Hdim + c];
    split1(Cg * acc, &Yh[(size_t)row * Hdim + c], &Yl[(size_t)row * Hdim + c]);
}

// ---------------- silu(gate)*up from fused [gate|up] buffer -> bf16 hi/lo ----------------
__global__ void silu_mul_split_kernel(const float* __restrict__ T,
                                      __nv_bfloat16* __restrict__ Hh, __nv_bfloat16* __restrict__ Hl) {
    int idx = blockIdx.x * blockDim.x + threadIdx.x;   // ROWS*IM
    int row = idx / IM, c = idx - row * IM;
    float g = T[(size_t)row * GUN + c];
    float u = T[(size_t)row * GUN + IM + c];
    float y = (g / (1.0f + expf(-g))) * u;
    split1(y, &Hh[idx], &Hl[idx]);
}

// ---------------- host-side plumbing ----------------
static void gemm(const __nv_bfloat16* Ah, const __nv_bfloat16* Al,
                 const __nv_bfloat16* Bh, const __nv_bfloat16* Bl,
                 float* C, int M, int N, int K, const float* bias, const float* res) {
    dim3 grid(M / 128, N / 128);           // M fast -> B-tile L2 reuse
    gemm_bf16x3<<<grid, 256, SMEM_TOTAL>>>(Ah, Al, Bh, Bl, C, M, N, K, bias, res);
}

extern "C" void kernel_launch(void* const* d_in, const int* in_sizes, int n_in,
                              void* d_out, int out_size) {
    const int*   tokens  = (const int*)  d_in[0];
    const float* embed   = (const float*)d_in[1];
    const float* qw      = (const float*)d_in[2];
    const float* kw      = (const float*)d_in[3];
    const float* vw      = (const float*)d_in[4];
    const float* ow      = (const float*)d_in[5];
    const float* qln     = (const float*)d_in[6];
    const float* kln     = (const float*)d_in[7];
    const float* a_gate  = (const float*)d_in[8];
    const float* a_up    = (const float*)d_in[9];
    const float* a_down  = (const float*)d_in[10];
    const float* a_ln1   = (const float*)d_in[11];
    const float* a_ln2   = (const float*)d_in[12];
    const float* conv_w  = (const float*)d_in[13];
    const float* conv_b  = (const float*)d_in[14];
    const float* in_w    = (const float*)d_in[15];
    const float* in_b    = (const float*)d_in[16];
    const float* out_w   = (const float*)d_in[17];
    const float* out_b   = (const float*)d_in[18];
    const float* c_gate  = (const float*)d_in[19];
    const float* c_up    = (const float*)d_in[20];
    const float* c_down  = (const float*)d_in[21];
    const float* c_ln1   = (const float*)d_in[22];
    const float* c_ln2   = (const float*)d_in[23];
    const float* finln   = (const float*)d_in[24];
    const float* lm_head = (const float*)d_in[25];

    cudaFuncSetAttribute(gemm_bf16x3, cudaFuncAttributeMaxDynamicSharedMemorySize, SMEM_TOTAL);

    float *x, *qkv, *t1, *t12;
    __nv_bfloat16 *ah, *al, *wh, *wl;
    cudaGetSymbolAddress((void**)&x,   g_x);
    cudaGetSymbolAddress((void**)&qkv, g_qkv);
    cudaGetSymbolAddress((void**)&t1,  g_t1);
    cudaGetSymbolAddress((void**)&t12, g_t12);
    cudaGetSymbolAddress((void**)&ah,  g_ah);
    cudaGetSymbolAddress((void**)&al,  g_al);
    cudaGetSymbolAddress((void**)&wh,  g_wh);
    cudaGetSymbolAddress((void**)&wl,  g_wl);

    // ---- build the single weight-split plan (42 segments) ----
    WPlan plan;
    long long cum = 0;
    int si = 0;
    auto seg = [&](const float* src, unsigned long long dst_elems, long long n_elems) {
        plan.s[si].src  = (const float4*)src;
        plan.s[si].dst4 = (long long)(dst_elems / 4);
        cum += n_elems / 4;
        plan.s[si].end4 = cum;
        si++;
    };
    for (int ai = 0; ai < 4; ai++) {
        unsigned long long d = OFF_QKV + (unsigned long long)ai * QKVN * Hdim;
        seg(qw + (size_t)ai * 589824, d,          589824);
        seg(kw + (size_t)ai * 196608, d + 589824, 196608);
        seg(vw + (size_t)ai * 196608, d + 786432, 196608);
    }
    seg(ow, OFF_OW, 2359296);
    for (int ai = 0; ai < 4; ai++) {
        unsigned long long d = OFF_AGU + (unsigned long long)ai * GUN * Hdim;
        seg(a_gate + (size_t)ai * 2359296, d,           2359296);
        seg(a_up   + (size_t)ai * 2359296, d + 2359296, 2359296);
    }
    seg(a_down, OFF_AD,   9437184);
    seg(in_w,   OFF_INW,  14155776);
    seg(out_w,  OFF_OUTW, 4718592);
    for (int ci = 0; ci < 8; ci++) {
        unsigned long long d = OFF_CGU + (unsigned long long)ci * GUN * Hdim;
        seg(c_gate + (size_t)ci * 2359296, d,           2359296);
        seg(c_up   + (size_t)ci * 2359296, d + 2359296, 2359296);
    }
    seg(c_down,  OFF_CD, 18874368);
    seg(lm_head, OFF_LM, 38633472);

    long long total4 = (long long)(W_TOTAL / 4);
    wsplit_all_kernel<<<(unsigned)((total4 + 255) / 256), 256>>>(plan, wh, wl, total4);

    embed_kernel<<<ROWS, 256>>>(tokens, embed, x);

    int ai = 0, ci = 0;
    for (int l = 0; l < 12; l++) {
        bool full = (l == 2 || l == 5 || l == 8 || l == 11);
        if (full) {
            size_t oqkv = OFF_QKV + (size_t)ai * QKVN * Hdim;
            size_t oo   = OFF_OW  + (size_t)ai * Hdim * Hdim;
            size_t ogu  = OFF_AGU + (size_t)ai * GUN * Hdim;
            size_t od   = OFF_AD  + (size_t)ai * Hdim * IM;
            rmsnorm_split_kernel<<<ROWS, 256>>>(x, a_ln1 + (size_t)ai * Hdim, ah, al, Hdim);
            gemm(ah, al, wh + oqkv, wl + oqkv, qkv, ROWS, QKVN, Hdim, 0, 0);
            qknorm_rope_kernel<<<ROWS * 16 / 8, 256>>>(qkv, qln + (size_t)ai * HD, kln + (size_t)ai * HD);
            attn_kernel<<<BATCH * NH * SEQ / 8, 256>>>(qkv, ah, al);
            gemm(ah, al, wh + oo, wl + oo, x, ROWS, Hdim, Hdim, 0, x);
            rmsnorm_split_kernel<<<ROWS, 256>>>(x, a_ln2 + (size_t)ai * Hdim, ah, al, Hdim);
            gemm(ah, al, wh + ogu, wl + ogu, t12, ROWS, GUN, Hdim, 0, 0);
            silu_mul_split_kernel<<<(ROWS * IM) / 256, 256>>>(t12, ah, al);
            gemm(ah, al, wh + od, wl + od, x, ROWS, Hdim, IM, 0, x);
            ai++;
        } else {
            size_t oi  = OFF_INW  + (size_t)ci * H3 * Hdim;
            size_t oo  = OFF_OUTW + (size_t)ci * Hdim * Hdim;
            size_t ogu = OFF_CGU  + (size_t)ci * GUN * Hdim;
            size_t od  = OFF_CD   + (size_t)ci * Hdim * IM;
            rmsnorm_split_kernel<<<ROWS, 256>>>(x, c_ln1 + (size_t)ci * Hdim, ah, al, Hdim);
            gemm(ah, al, wh + oi, wl + oi, t1, ROWS, H3, Hdim, in_b + (size_t)ci * H3, 0);
            conv_split_kernel<<<(ROWS * Hdim) / 256, 256>>>(t1, conv_w + (size_t)ci * Hdim * KCONV,
                                                            conv_b + (size_t)ci * Hdim, ah, al);
            gemm(ah, al, wh + oo, wl + oo, x, ROWS, Hdim, Hdim, out_b + (size_t)ci * Hdim, x);
            rmsnorm_split_kernel<<<ROWS, 256>>>(x, c_ln2 + (size_t)ci * Hdim, ah, al, Hdim);
            gemm(ah, al, wh + ogu, wl + ogu, t12, ROWS, GUN, Hdim, 0, 0);
            silu_mul_split_kernel<<<(ROWS * IM) / 256, 256>>>(t12, ah, al);
            gemm(ah, al, wh + od, wl + od, x, ROWS, Hdim, IM, 0, x);
            ci++;
        }
    }
    rmsnorm_split_kernel<<<ROWS, 256>>>(x, finln, ah, al, Hdim);
    gemm(ah, al, wh + OFF_LM, wl + OFF_LM, (float*)d_out, ROWS, VOCAB, Hdim, 0, 0);
}

// round 11
// speedup vs baseline: 2.2993x; 1.2931x over previous
#include <cuda_runtime.h>
#include <cuda_bf16.h>
#include <math.h>
#include <stdint.h>

// ---------------- constants ----------------
#define Hdim 768
#define NH 12
#define NKV 4
#define HD 64
#define IM 3072
#define KCONV 4
#define SEQ 1024
#define BATCH 2
#define ROWS (BATCH*SEQ)      // 2048
#define VOCAB 50304
#define H3 (3*Hdim)           // 2304
#define QKVN 1280             // 768 + 256 + 256
#define GUN  (2*IM)           // 6144

#define BK 32
#define NST 3

// ---------------- packed weight offsets (elems) ----------------
#define OFF_QKV  0ull
#define OFF_OW   3932160ull
#define OFF_AGU  6291456ull
#define OFF_AD   25165824ull
#define OFF_INW  34603008ull
#define OFF_OUTW 48758784ull
#define OFF_CGU  53477376ull
#define OFF_CD   91226112ull
#define OFF_LM   110100480ull
#define W_TOTAL  148733952ull

// ---------------- scratch ----------------
__device__ float g_x  [ROWS*Hdim];
__device__ float g_qkv[ROWS*QKVN];
__device__ float g_t1 [ROWS*H3];
__device__ float g_t12[ROWS*GUN];
__device__ __nv_bfloat16 g_ah[ROWS*IM];
__device__ __nv_bfloat16 g_al[ROWS*IM];
__device__ __nv_bfloat16 g_wh[W_TOTAL];
__device__ __nv_bfloat16 g_wl[W_TOTAL];

// ---------------- helpers ----------------
__device__ __forceinline__ void split1(float x, __nv_bfloat16* h, __nv_bfloat16* l) {
    __nv_bfloat16 hh = __float2bfloat16(x);
    *h = hh;
    *l = __float2bfloat16(x - __bfloat162float(hh));
}
__device__ __forceinline__ unsigned cvta_s(const void* p) {
    return (unsigned)__cvta_generic_to_shared(p);
}
__device__ __forceinline__ void cp16(unsigned saddr, const void* g) {
    asm volatile("cp.async.cg.shared.global [%0], [%1], 16;\n" :: "r"(saddr), "l"(g));
}
__device__ __forceinline__ void ldm4(unsigned* r, unsigned addr) {
    asm volatile("ldmatrix.sync.aligned.m8n8.x4.shared.b16 {%0,%1,%2,%3}, [%4];\n"
                 : "=r"(r[0]), "=r"(r[1]), "=r"(r[2]), "=r"(r[3]) : "r"(addr));
}
__device__ __forceinline__ void mma16816(float* d, const unsigned* a, const unsigned* b) {
    asm volatile("mma.sync.aligned.m16n8k16.row.col.f32.bf16.bf16.f32 "
                 "{%0,%1,%2,%3}, {%4,%5,%6,%7}, {%8,%9}, {%0,%1,%2,%3};\n"
                 : "+f"(d[0]), "+f"(d[1]), "+f"(d[2]), "+f"(d[3])
                 : "r"(a[0]), "r"(a[1]), "r"(a[2]), "r"(a[3]), "r"(b[0]), "r"(b[1]));
}
__device__ __forceinline__ unsigned sw_addr(unsigned base, int row, int col) {
    int u = col >> 3;
    return base + row * 64 + ((u ^ ((row >> 1) & 3)) << 4);
}

// ================= bf16x3 split GEMM, 3-stage swizzled, M-tile templated =================
// TM=2 -> 128x128 tile; TM=1 -> 64x128 tile (<=128 regs, 2 CTAs/SM).
// grid = (M/(64*TM), N/128), M fast.
template<int TM>
__global__ void __launch_bounds__(256, 3 - TM) gemm_bf16x3(
    const __nv_bfloat16* __restrict__ Ah, const __nv_bfloat16* __restrict__ Al,
    const __nv_bfloat16* __restrict__ Bh, const __nv_bfloat16* __restrict__ Bl,
    float* __restrict__ C, int M, int N, int K,
    const float* __restrict__ bias, const float* __restrict__ res)
{
    constexpr int MR      = 64 * TM;         // A rows per tile
    constexpr int ARR_A   = MR * 64;         // bytes per A array
    constexpr int ARR_Bb  = 8192;            // bytes per B array (128 rows x 64B)
    constexpr int STAGE   = 2 * ARR_A + 2 * ARR_Bb;
    constexpr int ALD     = MR * 8;          // float4 loads for both A arrays
    constexpr int NLDIT   = (ALD + 1024) / 256;

    extern __shared__ __align__(16) char sm_raw[];
    const int tid = threadIdx.x;
    const int lane = tid & 31, wid = tid >> 5;
    const int wm = wid >> 1, wn = wid & 1;
    const int bm = blockIdx.x * MR, bn = blockIdx.y * 128;
    const unsigned sbase = cvta_s(sm_raw);

    const __nv_bfloat16* gpA[2] = { Ah + (size_t)bm * K, Al + (size_t)bm * K };
    const __nv_bfloat16* gpB[2] = { Bh + (size_t)bn * K, Bl + (size_t)bn * K };

    float acc[TM][8][4];
    #pragma unroll
    for (int t = 0; t < TM; t++)
        #pragma unroll
        for (int n = 0; n < 8; n++)
            #pragma unroll
            for (int i = 0; i < 4; i++) acc[t][n][i] = 0.f;

    auto load_chunk = [&](int st, int c) {
        int gk = c * BK;
        unsigned sb = sbase + st * STAGE;
        #pragma unroll
        for (int i = 0; i < NLDIT; i++) {
            int idx = tid + i * 256;
            if (idx < ALD) {
                int arr = idx / (MR * 4);
                int j = idx - arr * (MR * 4);
                int r = j >> 2, u = j & 3;
                unsigned sa = sb + arr * ARR_A + r * 64 + ((u ^ ((r >> 1) & 3)) << 4);
                cp16(sa, gpA[arr] + (size_t)r * K + gk + u * 8);
            } else {
                int x = idx - ALD;
                int arr = x >> 9;
                int j = x & 511;
                int r = j >> 2, u = j & 3;
                unsigned sa = sb + 2 * ARR_A + arr * ARR_Bb + r * 64 + ((u ^ ((r >> 1) & 3)) << 4);
                cp16(sa, gpB[arr] + (size_t)r * K + gk + u * 8);
            }
        }
        asm volatile("cp.async.commit_group;\n");
    };

    const int KT = K / BK;
    load_chunk(0, 0);
    load_chunk(1, 1);

    for (int c = 0; c < KT; c++) {
        if (c + 1 < KT) asm volatile("cp.async.wait_group 1;\n");
        else            asm volatile("cp.async.wait_group 0;\n");
        __syncthreads();
        if (c + 2 < KT) load_chunk((c + 2) % NST, c + 2);

        unsigned st = sbase + (c % NST) * STAGE;
        #pragma unroll
        for (int kk = 0; kk < BK; kk += 16) {
            unsigned ah[TM][4], al[TM][4], bh[8][2], bl[8][2];
            #pragma unroll
            for (int t = 0; t < TM; t++) {
                int row = wm * (16 * TM) + t * 16 + (lane & 15);
                int col = kk + ((lane >> 4) << 3);
                ldm4(ah[t], sw_addr(st,          row, col));
                ldm4(al[t], sw_addr(st + ARR_A,  row, col));
            }
            #pragma unroll
            for (int p = 0; p < 4; p++) {
                int m = lane >> 3;
                int row = wn * 64 + p * 16 + ((m >> 1) << 3) + (lane & 7);
                int col = kk + ((m & 1) << 3);
                unsigned r[4];
                ldm4(r, sw_addr(st + 2 * ARR_A,           row, col));
                bh[2 * p][0] = r[0]; bh[2 * p][1] = r[1];
                bh[2 * p + 1][0] = r[2]; bh[2 * p + 1][1] = r[3];
                ldm4(r, sw_addr(st + 2 * ARR_A + ARR_Bb,  row, col));
                bl[2 * p][0] = r[0]; bl[2 * p][1] = r[1];
                bl[2 * p + 1][0] = r[2]; bl[2 * p + 1][1] = r[3];
            }
            #pragma unroll
            for (int t = 0; t < TM; t++)
                #pragma unroll
                for (int n = 0; n < 8; n++) {
                    mma16816(acc[t][n], ah[t], bh[n]);
                    mma16816(acc[t][n], ah[t], bl[n]);
                    mma16816(acc[t][n], al[t], bh[n]);
                }
        }
    }

    #pragma unroll
    for (int t = 0; t < TM; t++) {
        int row0 = bm + wm * (16 * TM) + t * 16 + (lane >> 2);
        #pragma unroll
        for (int n = 0; n < 8; n++) {
            int col = bn + wn * 64 + n * 8 + (lane & 3) * 2;
            #pragma unroll
            for (int hh = 0; hh < 2; hh++) {
                int row = row0 + hh * 8;
                float v0 = acc[t][n][hh * 2], v1 = acc[t][n][hh * 2 + 1];
                if (bias) { v0 += bias[col]; v1 += bias[col + 1]; }
                if (res) {
                    const float* rp = res + (size_t)row * N + col;
                    v0 += rp[0]; v1 += rp[1];
                }
                *(float2*)(C + (size_t)row * N + col) = make_float2(v0, v1);
            }
        }
    }
}

#define SMEM_TM2 (NST * (2*8192 + 2*8192))   // 98304
#define SMEM_TM1 (NST * (2*4096 + 2*8192))   // 73728

// ---------------- single fused weight-split kernel (32B/thread) ----------------
#define NSEG 42
struct WSeg { const float4* src; long long dst8; long long end8; };
struct WPlan { WSeg s[NSEG]; };

__global__ void wsplit_all_kernel(WPlan p, __nv_bfloat16* __restrict__ H,
                                  __nv_bfloat16* __restrict__ L, long long total8) {
    long long idx = (long long)blockIdx.x * 256 + threadIdx.x;
    if (idx >= total8) return;
    int lo = 0, hi = NSEG - 1;
    while (lo < hi) { int mid = (lo + hi) >> 1; if (idx < p.s[mid].end8) hi = mid; else lo = mid + 1; }
    long long start = lo ? p.s[lo - 1].end8 : 0;
    long long off = idx - start;
    const float4* sp = p.s[lo].src + off * 2;
    float4 v0 = sp[0], v1 = sp[1];
    __nv_bfloat16 h[8], l[8];
    split1(v0.x, &h[0], &l[0]); split1(v0.y, &h[1], &l[1]);
    split1(v0.z, &h[2], &l[2]); split1(v0.w, &h[3], &l[3]);
    split1(v1.x, &h[4], &l[4]); split1(v1.y, &h[5], &l[5]);
    split1(v1.z, &h[6], &l[6]); split1(v1.w, &h[7], &l[7]);
    long long d = p.s[lo].dst8 + off;
    *(uint4*)(H + d * 8) = *(uint4*)h;
    *(uint4*)(L + d * 8) = *(uint4*)l;
}

// ---------------- embedding gather ----------------
__global__ void embed_kernel(const int* __restrict__ tok, const float* __restrict__ E,
                             float* __restrict__ X) {
    int row = blockIdx.x;
    int t = tok[row];
    const float* src = E + (size_t)t * Hdim;
    float* dst = X + (size_t)row * Hdim;
    for (int c = threadIdx.x; c < Hdim; c += blockDim.x) dst[c] = src[c];
}

// ---------------- rmsnorm -> bf16 hi/lo ----------------
__global__ void rmsnorm_split_kernel(const float* __restrict__ X, const float* __restrict__ W,
                                     __nv_bfloat16* __restrict__ Hh, __nv_bfloat16* __restrict__ Hl,
                                     int n) {
    int row = blockIdx.x;
    const float* x = X + (size_t)row * n;
    float s = 0.f;
    for (int c = threadIdx.x; c < n; c += blockDim.x) { float v = x[c]; s += v * v; }
    __shared__ float sm[32];
    #pragma unroll
    for (int o = 16; o; o >>= 1) s += __shfl_xor_sync(~0u, s, o);
    if ((threadIdx.x & 31) == 0) sm[threadIdx.x >> 5] = s;
    __syncthreads();
    if (threadIdx.x < 32) {
        float v = (threadIdx.x < (blockDim.x >> 5)) ? sm[threadIdx.x] : 0.f;
        #pragma unroll
        for (int o = 4; o; o >>= 1) v += __shfl_xor_sync(~0u, v, o);
        if (threadIdx.x == 0) sm[0] = v;
    }
    __syncthreads();
    float r = rsqrtf(sm[0] / (float)n + 1e-6f);
    for (int c = threadIdx.x; c < n; c += blockDim.x) {
        float y = x[c] * r * W[c];
        split1(y, &Hh[(size_t)row * n + c], &Hl[(size_t)row * n + c]);
    }
}

// ---------------- per-head RMSNorm (q/k) + RoPE on fused QKV buffer ----------------
__global__ void qknorm_rope_kernel(float* __restrict__ QKV,
                                   const float* __restrict__ qln, const float* __restrict__ kln) {
    int w = threadIdx.x >> 5, l = threadIdx.x & 31;
    int g = blockIdx.x * 8 + w;
    int hh = g & 15;
    int row = g >> 4;
    int s = row & (SEQ - 1);
    float* p; const float* wn;
    if (hh < NH) { p = QKV + (size_t)row * QKVN + hh * HD;               wn = qln; }
    else         { p = QKV + (size_t)row * QKVN + 768 + (hh - NH) * HD;  wn = kln; }
    float a = p[l], b = p[l + 32];
    float ss = a * a + b * b;
    #pragma unroll
    for (int o = 16; o; o >>= 1) ss += __shfl_xor_sync(~0u, ss, o);
    float r = rsqrtf(ss * (1.0f / HD) + 1e-6f);
    a *= r * wn[l];
    b *= r * wn[l + 32];
    float inv = powf(10000.0f, -((float)l) / 32.0f);
    float ang = (float)s * inv;
    float cs = cosf(ang), sn = sinf(ang);
    p[l]      = a * cs - b * sn;
    p[l + 32] = b * cs + a * sn;
}

// ---------------- causal attention V2: smem K/V tiles, same FP order ----------------
#define KTILE 128
#define KVP 68          // padded row stride (floats): conflict-free for both phases
__global__ void __launch_bounds__(256) attn_kernel(
    const float* __restrict__ QKV,
    __nv_bfloat16* __restrict__ Oh, __nv_bfloat16* __restrict__ Ol) {
    __shared__ float qs[8][HD];
    __shared__ float sc[8][SEQ];
    __shared__ float kv[KTILE][KVP];
    int w = threadIdx.x >> 5, l = threadIdx.x & 31;
    int g = blockIdx.x * 8 + w;
    int s = g & (SEQ - 1);
    int bh = g >> 10;                  // same for all 8 warps in this block
    int h = bh % NH, b = bh / NH;
    int kvh = h / (NH / NKV);
    int s0 = (blockIdx.x * 8) & (SEQ - 1);
    int smax = s0 + 7;
    int ntile = smax / KTILE + 1;

    const float* qp = QKV + (size_t)(b * SEQ + s) * QKVN + h * HD;
    qs[w][l] = qp[l]; qs[w][l + 32] = qp[l + 32];
    __syncwarp();
    const float* Kb = QKV + (size_t)b * SEQ * QKVN + 768 + kvh * HD;
    const float* Vb = QKV + (size_t)b * SEQ * QKVN + 1024 + kvh * HD;

    // ---- QK phase: K tiles through smem ----
    for (int jt = 0; jt < ntile; jt++) {
        __syncthreads();
        for (int i = threadIdx.x; i < KTILE * 16; i += 256) {
            int key = i >> 4, d4 = i & 15;
            *(float4*)&kv[key][d4 * 4] =
                *(const float4*)(Kb + (size_t)(jt * KTILE + key) * QKVN + d4 * 4);
        }
        __syncthreads();
        int jend = jt * KTILE + KTILE - 1; if (jend > s) jend = s;
        for (int j = jt * KTILE + l; j <= jend; j += 32) {
            const float* kr = kv[j - jt * KTILE];
            float d = 0.f;
            #pragma unroll
            for (int i = 0; i < 16; i++) {
                float4 kk = *(const float4*)&kr[4 * i];
                d += qs[w][4*i] * kk.x + qs[w][4*i+1] * kk.y + qs[w][4*i+2] * kk.z + qs[w][4*i+3] * kk.w;
            }
            sc[w][j] = d * 0.125f;
        }
    }
    __syncwarp();
    // ---- softmax (unchanged) ----
    float m = -1e30f;
    for (int j = l; j <= s; j += 32) m = fmaxf(m, sc[w][j]);
    #pragma unroll
    for (int o = 16; o; o >>= 1) m = fmaxf(m, __shfl_xor_sync(~0u, m, o));
    float sum = 0.f;
    for (int j = l; j <= s; j += 32) { float p = expf(sc[w][j] - m); sc[w][j] = p; sum += p; }
    #pragma unroll
    for (int o = 16; o; o >>= 1) sum += __shfl_xor_sync(~0u, sum, o);
    __syncwarp();
    // ---- PV phase: V tiles through smem, ascending j (same FP order) ----
    float oa = 0.f, ob = 0.f;
    for (int jt = 0; jt < ntile; jt++) {
        __syncthreads();
        for (int i = threadIdx.x; i < KTILE * 16; i += 256) {
            int key = i >> 4, d4 = i & 15;
            *(float4*)&kv[key][d4 * 4] =
                *(const float4*)(Vb + (size_t)(jt * KTILE + key) * QKVN + d4 * 4);
        }
        __syncthreads();
        int jend = jt * KTILE + KTILE - 1; if (jend > s) jend = s;
        for (int j = jt * KTILE; j <= jend; j++) {
            float p = sc[w][j];
            const float* vr = kv[j - jt * KTILE];
            oa += p * vr[l]; ob += p * vr[l + 32];
        }
    }
    float invs = 1.0f / sum;
    size_t op = ((size_t)(b * SEQ + s) * NH + h) * HD;
    split1(oa * invs, &Oh[op + l], &Ol[op + l]);
    split1(ob * invs, &Oh[op + l + 32], &Ol[op + l + 32]);
}

// ---------------- causal depthwise conv -> bf16 hi/lo ----------------
__global__ void conv_split_kernel(const float* __restrict__ T, const float* __restrict__ W4,
                                  const float* __restrict__ cb,
                                  __nv_bfloat16* __restrict__ Yh, __nv_bfloat16* __restrict__ Yl) {
    int idx = blockIdx.x * blockDim.x + threadIdx.x;
    int c = idx % Hdim;
    int row = idx / Hdim;
    int s = row & (SEQ - 1);
    int b = row / SEQ;
    const float* w = W4 + (size_t)c * KCONV;
    float acc = cb[c];
    #pragma unroll
    for (int j = 0; j < KCONV; j++) {
        int sp = s - (KCONV - 1) + j;
        if (sp >= 0) {
            const float* tr = T + (size_t)(b * SEQ + sp) * H3;
            acc += w[j] * tr[c] * tr[2 * Hdim + c];
        }
    }
    float Cg = T[(size_t)row * H3 + Hdim + c];
    split1(Cg * acc, &Yh[(size_t)row * Hdim + c], &Yl[(size_t)row * Hdim + c]);
}

// ---------------- silu(gate)*up -> bf16 hi/lo ----------------
__global__ void silu_mul_split_kernel(const float* __restrict__ T,
                                      __nv_bfloat16* __restrict__ Hh, __nv_bfloat16* __restrict__ Hl) {
    int idx = blockIdx.x * blockDim.x + threadIdx.x;   // ROWS*IM
    int row = idx / IM, c = idx - row * IM;
    float g = T[(size_t)row * GUN + c];
    float u = T[(size_t)row * GUN + IM + c];
    float y = (g / (1.0f + expf(-g))) * u;
    split1(y, &Hh[idx], &Hl[idx]);
}

// ---------------- host-side plumbing ----------------
static void gemm(const __nv_bfloat16* Ah, const __nv_bfloat16* Al,
                 const __nv_bfloat16* Bh, const __nv_bfloat16* Bl,
                 float* C, int M, int N, int K, const float* bias, const float* res) {
    if (N <= 1280) {
        dim3 grid(M / 64, N / 128);
        gemm_bf16x3<1><<<grid, 256, SMEM_TM1>>>(Ah, Al, Bh, Bl, C, M, N, K, bias, res);
    } else {
        dim3 grid(M / 128, N / 128);
        gemm_bf16x3<2><<<grid, 256, SMEM_TM2>>>(Ah, Al, Bh, Bl, C, M, N, K, bias, res);
    }
}

extern "C" void kernel_launch(void* const* d_in, const int* in_sizes, int n_in,
                              void* d_out, int out_size) {
    const int*   tokens  = (const int*)  d_in[0];
    const float* embed   = (const float*)d_in[1];
    const float* qw      = (const float*)d_in[2];
    const float* kw      = (const float*)d_in[3];
    const float* vw      = (const float*)d_in[4];
    const float* ow      = (const float*)d_in[5];
    const float* qln     = (const float*)d_in[6];
    const float* kln     = (const float*)d_in[7];
    const float* a_gate  = (const float*)d_in[8];
    const float* a_up    = (const float*)d_in[9];
    const float* a_down  = (const float*)d_in[10];
    const float* a_ln1   = (const float*)d_in[11];
    const float* a_ln2   = (const float*)d_in[12];
    const float* conv_w  = (const float*)d_in[13];
    const float* conv_b  = (const float*)d_in[14];
    const float* in_w    = (const float*)d_in[15];
    const float* in_b    = (const float*)d_in[16];
    const float* out_w   = (const float*)d_in[17];
    const float* out_b   = (const float*)d_in[18];
    const float* c_gate  = (const float*)d_in[19];
    const float* c_up    = (const float*)d_in[20];
    const float* c_down  = (const float*)d_in[21];
    const float* c_ln1   = (const float*)d_in[22];
    const float* c_ln2   = (const float*)d_in[23];
    const float* finln   = (const float*)d_in[24];
    const float* lm_head = (const float*)d_in[25];

    cudaFuncSetAttribute(gemm_bf16x3<1>, cudaFuncAttributeMaxDynamicSharedMemorySize, SMEM_TM1);
    cudaFuncSetAttribute(gemm_bf16x3<2>, cudaFuncAttributeMaxDynamicSharedMemorySize, SMEM_TM2);

    float *x, *qkv, *t1, *t12;
    __nv_bfloat16 *ah, *al, *wh, *wl;
    cudaGetSymbolAddress((void**)&x,   g_x);
    cudaGetSymbolAddress((void**)&qkv, g_qkv);
    cudaGetSymbolAddress((void**)&t1,  g_t1);
    cudaGetSymbolAddress((void**)&t12, g_t12);
    cudaGetSymbolAddress((void**)&ah,  g_ah);
    cudaGetSymbolAddress((void**)&al,  g_al);
    cudaGetSymbolAddress((void**)&wh,  g_wh);
    cudaGetSymbolAddress((void**)&wl,  g_wl);

    // ---- build the single weight-split plan (42 segments, 8-elem units) ----
    WPlan plan;
    long long cum = 0;
    int si = 0;
    auto seg = [&](const float* src, unsigned long long dst_elems, long long n_elems) {
        plan.s[si].src  = (const float4*)src;
        plan.s[si].dst8 = (long long)(dst_elems / 8);
        cum += n_elems / 8;
        plan.s[si].end8 = cum;
        si++;
    };
    for (int ai = 0; ai < 4; ai++) {
        unsigned long long d = OFF_QKV + (unsigned long long)ai * QKVN * Hdim;
        seg(qw + (size_t)ai * 589824, d,          589824);
        seg(kw + (size_t)ai * 196608, d + 589824, 196608);
        seg(vw + (size_t)ai * 196608, d + 786432, 196608);
    }
    seg(ow, OFF_OW, 2359296);
    for (int ai = 0; ai < 4; ai++) {
        unsigned long long d = OFF_AGU + (unsigned long long)ai * GUN * Hdim;
        seg(a_gate + (size_t)ai * 2359296, d,           2359296);
        seg(a_up   + (size_t)ai * 2359296, d + 2359296, 2359296);
    }
    seg(a_down, OFF_AD,   9437184);
    seg(in_w,   OFF_INW,  14155776);
    seg(out_w,  OFF_OUTW, 4718592);
    for (int ci = 0; ci < 8; ci++) {
        unsigned long long d = OFF_CGU + (unsigned long long)ci * GUN * Hdim;
        seg(c_gate + (size_t)ci * 2359296, d,           2359296);
        seg(c_up   + (size_t)ci * 2359296, d + 2359296, 2359296);
    }
    seg(c_down,  OFF_CD, 18874368);
    seg(lm_head, OFF_LM, 38633472);

    long long total8 = (long long)(W_TOTAL / 8);
    wsplit_all_kernel<<<(unsigned)((total8 + 255) / 256), 256>>>(plan, wh, wl, total8);

    embed_kernel<<<ROWS, 256>>>(tokens, embed, x);

    int ai = 0, ci = 0;
    for (int l = 0; l < 12; l++) {
        bool full = (l == 2 || l == 5 || l == 8 || l == 11);
        if (full) {
            size_t oqkv = OFF_QKV + (size_t)ai * QKVN * Hdim;
            size_t oo   = OFF_OW  + (size_t)ai * Hdim * Hdim;
            size_t ogu  = OFF_AGU + (size_t)ai * GUN * Hdim;
            size_t od   = OFF_AD  + (size_t)ai * Hdim * IM;
            rmsnorm_split_kernel<<<ROWS, 256>>>(x, a_ln1 + (size_t)ai * Hdim, ah, al, Hdim);
            gemm(ah, al, wh + oqkv, wl + oqkv, qkv, ROWS, QKVN, Hdim, 0, 0);
            qknorm_rope_kernel<<<ROWS * 16 / 8, 256>>>(qkv, qln + (size_t)ai * HD, kln + (size_t)ai * HD);
            attn_kernel<<<BATCH * NH * SEQ / 8, 256>>>(qkv, ah, al);
            gemm(ah, al, wh + oo, wl + oo, x, ROWS, Hdim, Hdim, 0, x);
            rmsnorm_split_kernel<<<ROWS, 256>>>(x, a_ln2 + (size_t)ai * Hdim, ah, al, Hdim);
            gemm(ah, al, wh + ogu, wl + ogu, t12, ROWS, GUN, Hdim, 0, 0);
            silu_mul_split_kernel<<<(ROWS * IM) / 256, 256>>>(t12, ah, al);
            gemm(ah, al, wh + od, wl + od, x, ROWS, Hdim, IM, 0, x);
            ai++;
        } else {
            size_t oi  = OFF_INW  + (size_t)ci * H3 * Hdim;
            size_t oo  = OFF_OUTW + (size_t)ci * Hdim * Hdim;
            size_t ogu = OFF_CGU  + (size_t)ci * GUN * Hdim;
            size_t od  = OFF_CD   + (size_t)ci * Hdim * IM;
            rmsnorm_split_kernel<<<ROWS, 256>>>(x, c_ln1 + (size_t)ci * Hdim, ah, al, Hdim);
            gemm(ah, al, wh + oi, wl + oi, t1, ROWS, H3, Hdim, in_b + (size_t)ci * H3, 0);
            conv_split_kernel<<<(ROWS * Hdim) / 256, 256>>>(t1, conv_w + (size_t)ci * Hdim * KCONV,
                                                            conv_b + (size_t)ci * Hdim, ah, al);
            gemm(ah, al, wh + oo, wl + oo, x, ROWS, Hdim, Hdim, out_b + (size_t)ci * Hdim, x);
            rmsnorm_split_kernel<<<ROWS, 256>>>(x, c_ln2 + (size_t)ci * Hdim, ah, al, Hdim);
            gemm(ah, al, wh + ogu, wl + ogu, t12, ROWS, GUN, Hdim, 0, 0);
            silu_mul_split_kernel<<<(ROWS * IM) / 256, 256>>>(t12, ah, al);
            gemm(ah, al, wh + od, wl + od, x, ROWS, Hdim, IM, 0, x);
            ci++;
        }
    }
    rmsnorm_split_kernel<<<ROWS, 256>>>(x, finln, ah, al, Hdim);
    gemm(ah, al, wh + OFF_LM, wl + OFF_LM, (float*)d_out, ROWS, VOCAB, Hdim, 0, 0);
}

// round 13
// speedup vs baseline: 2.3256x; 1.0114x over previous
#include <cuda_runtime.h>
#include <cuda_bf16.h>
#include <math.h>
#include <stdint.h>

// ---------------- constants ----------------
#define Hdim 768
#define NH 12
#define NKV 4
#define HD 64
#define IM 3072
#define KCONV 4
#define SEQ 1024
#define BATCH 2
#define ROWS (BATCH*SEQ)      // 2048
#define VOCAB 50304
#define H3 (3*Hdim)           // 2304
#define QKVN 1280             // 768 + 256 + 256
#define GUN  (2*IM)           // 6144

#define BK 32
#define NST 3

// ---------------- packed weight offsets (elems) ----------------
#define OFF_QKV  0ull
#define OFF_OW   3932160ull
#define OFF_AGU  6291456ull
#define OFF_AD   25165824ull
#define OFF_INW  34603008ull
#define OFF_OUTW 48758784ull
#define OFF_CGU  53477376ull
#define OFF_CD   91226112ull
#define OFF_LM   110100480ull
#define W_TOTAL  148733952ull

// ---------------- scratch ----------------
__device__ float g_x  [ROWS*Hdim];
__device__ float g_qkv[ROWS*QKVN];
__device__ float g_t1 [ROWS*H3];
__device__ float g_t12[ROWS*GUN];
__device__ __nv_bfloat16 g_ah[ROWS*IM];
__device__ __nv_bfloat16 g_al[ROWS*IM];
__device__ __nv_bfloat16 g_wh[W_TOTAL];
__device__ __nv_bfloat16 g_wl[W_TOTAL];

// ---------------- helpers ----------------
__device__ __forceinline__ void split1(float x, __nv_bfloat16* h, __nv_bfloat16* l) {
    __nv_bfloat16 hh = __float2bfloat16(x);
    *h = hh;
    *l = __float2bfloat16(x - __bfloat162float(hh));
}
__device__ __forceinline__ unsigned cvta_s(const void* p) {
    return (unsigned)__cvta_generic_to_shared(p);
}
__device__ __forceinline__ void cp16(unsigned saddr, const void* g) {
    asm volatile("cp.async.cg.shared.global [%0], [%1], 16;\n" :: "r"(saddr), "l"(g));
}
__device__ __forceinline__ void ldm4(unsigned* r, unsigned addr) {
    asm volatile("ldmatrix.sync.aligned.m8n8.x4.shared.b16 {%0,%1,%2,%3}, [%4];\n"
                 : "=r"(r[0]), "=r"(r[1]), "=r"(r[2]), "=r"(r[3]) : "r"(addr));
}
__device__ __forceinline__ void mma16816(float* d, const unsigned* a, const unsigned* b) {
    asm volatile("mma.sync.aligned.m16n8k16.row.col.f32.bf16.bf16.f32 "
                 "{%0,%1,%2,%3}, {%4,%5,%6,%7}, {%8,%9}, {%0,%1,%2,%3};\n"
                 : "+f"(d[0]), "+f"(d[1]), "+f"(d[2]), "+f"(d[3])
                 : "r"(a[0]), "r"(a[1]), "r"(a[2]), "r"(a[3]), "r"(b[0]), "r"(b[1]));
}
__device__ __forceinline__ unsigned sw_addr(unsigned base, int row, int col) {
    int u = col >> 3;
    return base + row * 64 + ((u ^ ((row >> 1) & 3)) << 4);
}

// ================= bf16x3 split GEMM, 3-stage swizzled, M-tile templated =================
template<int TM>
__global__ void __launch_bounds__(256, 3 - TM) gemm_bf16x3(
    const __nv_bfloat16* __restrict__ Ah, const __nv_bfloat16* __restrict__ Al,
    const __nv_bfloat16* __restrict__ Bh, const __nv_bfloat16* __restrict__ Bl,
    float* __restrict__ C, int M, int N, int K,
    const float* __restrict__ bias, const float* __restrict__ res)
{
    constexpr int MR      = 64 * TM;
    constexpr int ARR_A   = MR * 64;
    constexpr int ARR_Bb  = 8192;
    constexpr int STAGE   = 2 * ARR_A + 2 * ARR_Bb;
    constexpr int ALD     = MR * 8;
    constexpr int NLDIT   = (ALD + 1024) / 256;

    extern __shared__ __align__(16) char sm_raw[];
    const int tid = threadIdx.x;
    const int lane = tid & 31, wid = tid >> 5;
    const int wm = wid >> 1, wn = wid & 1;
    const int bm = blockIdx.x * MR, bn = blockIdx.y * 128;
    const unsigned sbase = cvta_s(sm_raw);

    const __nv_bfloat16* gpA[2] = { Ah + (size_t)bm * K, Al + (size_t)bm * K };
    const __nv_bfloat16* gpB[2] = { Bh + (size_t)bn * K, Bl + (size_t)bn * K };

    float acc[TM][8][4];
    #pragma unroll
    for (int t = 0; t < TM; t++)
        #pragma unroll
        for (int n = 0; n < 8; n++)
            #pragma unroll
            for (int i = 0; i < 4; i++) acc[t][n][i] = 0.f;

    auto load_chunk = [&](int st, int c) {
        int gk = c * BK;
        unsigned sb = sbase + st * STAGE;
        #pragma unroll
        for (int i = 0; i < NLDIT; i++) {
            int idx = tid + i * 256;
            if (idx < ALD) {
                int arr = idx / (MR * 4);
                int j = idx - arr * (MR * 4);
                int r = j >> 2, u = j & 3;
                unsigned sa = sb + arr * ARR_A + r * 64 + ((u ^ ((r >> 1) & 3)) << 4);
                cp16(sa, gpA[arr] + (size_t)r * K + gk + u * 8);
            } else {
                int x = idx - ALD;
                int arr = x >> 9;
                int j = x & 511;
                int r = j >> 2, u = j & 3;
                unsigned sa = sb + 2 * ARR_A + arr * ARR_Bb + r * 64 + ((u ^ ((r >> 1) & 3)) << 4);
                cp16(sa, gpB[arr] + (size_t)r * K + gk + u * 8);
            }
        }
        asm volatile("cp.async.commit_group;\n");
    };

    const int KT = K / BK;
    load_chunk(0, 0);
    load_chunk(1, 1);

    for (int c = 0; c < KT; c++) {
        if (c + 1 < KT) asm volatile("cp.async.wait_group 1;\n");
        else            asm volatile("cp.async.wait_group 0;\n");
        __syncthreads();
        if (c + 2 < KT) load_chunk((c + 2) % NST, c + 2);

        unsigned st = sbase + (c % NST) * STAGE;
        #pragma unroll
        for (int kk = 0; kk < BK; kk += 16) {
            unsigned ah[TM][4], al[TM][4], bh[8][2], bl[8][2];
            #pragma unroll
            for (int t = 0; t < TM; t++) {
                int row = wm * (16 * TM) + t * 16 + (lane & 15);
                int col = kk + ((lane >> 4) << 3);
                ldm4(ah[t], sw_addr(st,          row, col));
                ldm4(al[t], sw_addr(st + ARR_A,  row, col));
            }
            #pragma unroll
            for (int p = 0; p < 4; p++) {
                int m = lane >> 3;
                int row = wn * 64 + p * 16 + ((m >> 1) << 3) + (lane & 7);
                int col = kk + ((m & 1) << 3);
                unsigned r[4];
                ldm4(r, sw_addr(st + 2 * ARR_A,           row, col));
                bh[2 * p][0] = r[0]; bh[2 * p][1] = r[1];
                bh[2 * p + 1][0] = r[2]; bh[2 * p + 1][1] = r[3];
                ldm4(r, sw_addr(st + 2 * ARR_A + ARR_Bb,  row, col));
                bl[2 * p][0] = r[0]; bl[2 * p][1] = r[1];
                bl[2 * p + 1][0] = r[2]; bl[2 * p + 1][1] = r[3];
            }
            #pragma unroll
            for (int t = 0; t < TM; t++)
                #pragma unroll
                for (int n = 0; n < 8; n++) {
                    mma16816(acc[t][n], ah[t], bh[n]);
                    mma16816(acc[t][n], ah[t], bl[n]);
                    mma16816(acc[t][n], al[t], bh[n]);
                }
        }
    }

    #pragma unroll
    for (int t = 0; t < TM; t++) {
        int row0 = bm + wm * (16 * TM) + t * 16 + (lane >> 2);
        #pragma unroll
        for (int n = 0; n < 8; n++) {
            int col = bn + wn * 64 + n * 8 + (lane & 3) * 2;
            #pragma unroll
            for (int hh = 0; hh < 2; hh++) {
                int row = row0 + hh * 8;
                float v0 = acc[t][n][hh * 2], v1 = acc[t][n][hh * 2 + 1];
                if (bias) { v0 += bias[col]; v1 += bias[col + 1]; }
                if (res) {
                    const float* rp = res + (size_t)row * N + col;
                    v0 += rp[0]; v1 += rp[1];
                }
                *(float2*)(C + (size_t)row * N + col) = make_float2(v0, v1);
            }
        }
    }
}

#define SMEM_TM2 (NST * (2*8192 + 2*8192))   // 98304
#define SMEM_TM1 (NST * (2*4096 + 2*8192))   // 73728

// ---------------- fused weight-split kernel (32B/thread) ----------------
#define NSEG 42
struct WSeg { const float4* src; long long dst8; long long end8; };
struct WPlan { WSeg s[NSEG]; };

__global__ void wsplit_all_kernel(WPlan p, __nv_bfloat16* __restrict__ H,
                                  __nv_bfloat16* __restrict__ L, long long total8) {
    long long idx = (long long)blockIdx.x * 256 + threadIdx.x;
    if (idx >= total8) return;
    int lo = 0, hi = NSEG - 1;
    while (lo < hi) { int mid = (lo + hi) >> 1; if (idx < p.s[mid].end8) hi = mid; else lo = mid + 1; }
    long long start = lo ? p.s[lo - 1].end8 : 0;
    long long off = idx - start;
    const float4* sp = p.s[lo].src + off * 2;
    float4 v0 = sp[0], v1 = sp[1];
    __nv_bfloat16 h[8], l[8];
    split1(v0.x, &h[0], &l[0]); split1(v0.y, &h[1], &l[1]);
    split1(v0.z, &h[2], &l[2]); split1(v0.w, &h[3], &l[3]);
    split1(v1.x, &h[4], &l[4]); split1(v1.y, &h[5], &l[5]);
    split1(v1.z, &h[6], &l[6]); split1(v1.w, &h[7], &l[7]);
    long long d = p.s[lo].dst8 + off;
    *(uint4*)(H + d * 8) = *(uint4*)h;
    *(uint4*)(L + d * 8) = *(uint4*)l;
}

// ---------------- embedding gather ----------------
__global__ void embed_kernel(const int* __restrict__ tok, const float* __restrict__ E,
                             float* __restrict__ X) {
    int row = blockIdx.x;
    int t = tok[row];
    const float* src = E + (size_t)t * Hdim;
    float* dst = X + (size_t)row * Hdim;
    for (int c = threadIdx.x; c < Hdim; c += blockDim.x) dst[c] = src[c];
}

// ---------------- rmsnorm -> bf16 hi/lo ----------------
__global__ void rmsnorm_split_kernel(const float* __restrict__ X, const float* __restrict__ W,
                                     __nv_bfloat16* __restrict__ Hh, __nv_bfloat16* __restrict__ Hl,
                                     int n) {
    int row = blockIdx.x;
    const float* x = X + (size_t)row * n;
    float s = 0.f;
    for (int c = threadIdx.x; c < n; c += blockDim.x) { float v = x[c]; s += v * v; }
    __shared__ float sm[32];
    #pragma unroll
    for (int o = 16; o; o >>= 1) s += __shfl_xor_sync(~0u, s, o);
    if ((threadIdx.x & 31) == 0) sm[threadIdx.x >> 5] = s;
    __syncthreads();
    if (threadIdx.x < 32) {
        float v = (threadIdx.x < (blockDim.x >> 5)) ? sm[threadIdx.x] : 0.f;
        #pragma unroll
        for (int o = 4; o; o >>= 1) v += __shfl_xor_sync(~0u, v, o);
        if (threadIdx.x == 0) sm[0] = v;
    }
    __syncthreads();
    float r = rsqrtf(sm[0] / (float)n + 1e-6f);
    for (int c = threadIdx.x; c < n; c += blockDim.x) {
        float y = x[c] * r * W[c];
        split1(y, &Hh[(size_t)row * n + c], &Hl[(size_t)row * n + c]);
    }
}

// ---------------- per-head RMSNorm (q/k) + RoPE on fused QKV buffer ----------------
__global__ void qknorm_rope_kernel(float* __restrict__ QKV,
                                   const float* __restrict__ qln, const float* __restrict__ kln) {
    int w = threadIdx.x >> 5, l = threadIdx.x & 31;
    int g = blockIdx.x * 8 + w;
    int hh = g & 15;
    int row = g >> 4;
    int s = row & (SEQ - 1);
    float* p; const float* wn;
    if (hh < NH) { p = QKV + (size_t)row * QKVN + hh * HD;               wn = qln; }
    else         { p = QKV + (size_t)row * QKVN + 768 + (hh - NH) * HD;  wn = kln; }
    float a = p[l], b = p[l + 32];
    float ss = a * a + b * b;
    #pragma unroll
    for (int o = 16; o; o >>= 1) ss += __shfl_xor_sync(~0u, ss, o);
    float r = rsqrtf(ss * (1.0f / HD) + 1e-6f);
    a *= r * wn[l];
    b *= r * wn[l + 32];
    float inv = powf(10000.0f, -((float)l) / 32.0f);
    float ang = (float)s * inv;
    float cs = cosf(ang), sn = sinf(ang);
    p[l]      = a * cs - b * sn;
    p[l + 32] = b * cs + a * sn;
}

// ---------------- causal attention V2: smem K/V tiles ----------------
#define KTILE 128
#define KVP 68
__global__ void __launch_bounds__(256) attn_kernel(
    const float* __restrict__ QKV,
    __nv_bfloat16* __restrict__ Oh, __nv_bfloat16* __restrict__ Ol) {
    __shared__ float qs[8][HD];
    __shared__ float sc[8][SEQ];
    __shared__ float kv[KTILE][KVP];
    int w = threadIdx.x >> 5, l = threadIdx.x & 31;
    int g = blockIdx.x * 8 + w;
    int s = g & (SEQ - 1);
    int bh = g >> 10;
    int h = bh % NH, b = bh / NH;
    int kvh = h / (NH / NKV);
    int s0 = (blockIdx.x * 8) & (SEQ - 1);
    int smax = s0 + 7;
    int ntile = smax / KTILE + 1;

    const float* qp = QKV + (size_t)(b * SEQ + s) * QKVN + h * HD;
    qs[w][l] = qp[l]; qs[w][l + 32] = qp[l + 32];
    __syncwarp();
    const float* Kb = QKV + (size_t)b * SEQ * QKVN + 768 + kvh * HD;
    const float* Vb = QKV + (size_t)b * SEQ * QKVN + 1024 + kvh * HD;

    for (int jt = 0; jt < ntile; jt++) {
        __syncthreads();
        for (int i = threadIdx.x; i < KTILE * 16; i += 256) {
            int key = i >> 4, d4 = i & 15;
            *(float4*)&kv[key][d4 * 4] =
                *(const float4*)(Kb + (size_t)(jt * KTILE + key) * QKVN + d4 * 4);
        }
        __syncthreads();
        int jend = jt * KTILE + KTILE - 1; if (jend > s) jend = s;
        for (int j = jt * KTILE + l; j <= jend; j += 32) {
            const float* kr = kv[j - jt * KTILE];
            float d = 0.f;
            #pragma unroll
            for (int i = 0; i < 16; i++) {
                float4 kk = *(const float4*)&kr[4 * i];
                d += qs[w][4*i] * kk.x + qs[w][4*i+1] * kk.y + qs[w][4*i+2] * kk.z + qs[w][4*i+3] * kk.w;
            }
            sc[w][j] = d * 0.125f;
        }
    }
    __syncwarp();
    float m = -1e30f;
    for (int j = l; j <= s; j += 32) m = fmaxf(m, sc[w][j]);
    #pragma unroll
    for (int o = 16; o; o >>= 1) m = fmaxf(m, __shfl_xor_sync(~0u, m, o));
    float sum = 0.f;
    for (int j = l; j <= s; j += 32) { float p = expf(sc[w][j] - m); sc[w][j] = p; sum += p; }
    #pragma unroll
    for (int o = 16; o; o >>= 1) sum += __shfl_xor_sync(~0u, sum, o);
    __syncwarp();
    float oa = 0.f, ob = 0.f;
    for (int jt = 0; jt < ntile; jt++) {
        __syncthreads();
        for (int i = threadIdx.x; i < KTILE * 16; i += 256) {
            int key = i >> 4, d4 = i & 15;
            *(float4*)&kv[key][d4 * 4] =
                *(const float4*)(Vb + (size_t)(jt * KTILE + key) * QKVN + d4 * 4);
        }
        __syncthreads();
        int jend = jt * KTILE + KTILE - 1; if (jend > s) jend = s;
        for (int j = jt * KTILE; j <= jend; j++) {
            float p = sc[w][j];
            const float* vr = kv[j - jt * KTILE];
            oa += p * vr[l]; ob += p * vr[l + 32];
        }
    }
    float invs = 1.0f / sum;
    size_t op = ((size_t)(b * SEQ + s) * NH + h) * HD;
    split1(oa * invs, &Oh[op + l], &Ol[op + l]);
    split1(ob * invs, &Oh[op + l + 32], &Ol[op + l + 32]);
}

// ---------------- causal depthwise conv -> bf16 hi/lo ----------------
__global__ void conv_split_kernel(const float* __restrict__ T, const float* __restrict__ W4,
                                  const float* __restrict__ cb,
                                  __nv_bfloat16* __restrict__ Yh, __nv_bfloat16* __restrict__ Yl) {
    int idx = blockIdx.x * blockDim.x + threadIdx.x;
    int c = idx % Hdim;
    int row = idx / Hdim;
    int s = row & (SEQ - 1);
    int b = row / SEQ;
    const float* w = W4 + (size_t)c * KCONV;
    float acc = cb[c];
    #pragma unroll
    for (int j = 0; j < KCONV; j++) {
        int sp = s - (KCONV - 1) + j;
        if (sp >= 0) {
            const float* tr = T + (size_t)(b * SEQ + sp) * H3;
            acc += w[j] * tr[c] * tr[2 * Hdim + c];
        }
    }
    float Cg = T[(size_t)row * H3 + Hdim + c];
    split1(Cg * acc, &Yh[(size_t)row * Hdim + c], &Yl[(size_t)row * Hdim + c]);
}

// ---------------- silu(gate)*up, vectorized x4 -> bf16 hi/lo ----------------
__global__ void silu_mul_split_kernel(const float* __restrict__ T,
                                      __nv_bfloat16* __restrict__ Hh, __nv_bfloat16* __restrict__ Hl) {
    int idx = blockIdx.x * blockDim.x + threadIdx.x;   // over ROWS*IM/4
    int row = idx / (IM / 4), c4 = idx - row * (IM / 4);
    const float4 g4 = *(const float4*)(T + (size_t)row * GUN + c4 * 4);
    const float4 u4 = *(const float4*)(T + (size_t)row * GUN + IM + c4 * 4);
    float gg[4] = { g4.x, g4.y, g4.z, g4.w };
    float uu[4] = { u4.x, u4.y, u4.z, u4.w };
    __nv_bfloat16 h[4], l[4];
    #pragma unroll
    for (int i = 0; i < 4; i++) {
        float g = gg[i];
        float y = (g / (1.0f + expf(-g))) * uu[i];
        split1(y, &h[i], &l[i]);
    }
    size_t d = (size_t)row * IM + c4 * 4;
    *(uint2*)(Hh + d) = *(uint2*)h;
    *(uint2*)(Hl + d) = *(uint2*)l;
}

// ---------------- host-side plumbing ----------------
static void gemm(const __nv_bfloat16* Ah, const __nv_bfloat16* Al,
                 const __nv_bfloat16* Bh, const __nv_bfloat16* Bl,
                 float* C, int M, int N, int K, const float* bias, const float* res) {
    if (N <= 1280) {
        dim3 grid(M / 64, N / 128);
        gemm_bf16x3<1><<<grid, 256, SMEM_TM1>>>(Ah, Al, Bh, Bl, C, M, N, K, bias, res);
    } else {
        dim3 grid(M / 128, N / 128);
        gemm_bf16x3<2><<<grid, 256, SMEM_TM2>>>(Ah, Al, Bh, Bl, C, M, N, K, bias, res);
    }
}

struct PlanBuilder {
    WPlan plan;
    long long cum = 0;
    int si = 0;
    void seg(const float* src, unsigned long long dst_elems, long long n_elems) {
        plan.s[si].src  = (const float4*)src;
        plan.s[si].dst8 = (long long)(dst_elems / 8);
        cum += n_elems / 8;
        plan.s[si].end8 = cum;
        si++;
    }
    void finalize() {
        for (int i = si; i < NSEG; i++) {
            plan.s[i].src = nullptr;
            plan.s[i].dst8 = 0;
            plan.s[i].end8 = cum;   // pad: never selected since idx < cum
        }
    }
};

extern "C" void kernel_launch(void* const* d_in, const int* in_sizes, int n_in,
                              void* d_out, int out_size) {
    const int*   tokens  = (const int*)  d_in[0];
    const float* embed   = (const float*)d_in[1];
    const float* qw      = (const float*)d_in[2];
    const float* kw      = (const float*)d_in[3];
    const float* vw      = (const float*)d_in[4];
    const float* ow      = (const float*)d_in[5];
    const float* qln     = (const float*)d_in[6];
    const float* kln     = (const float*)d_in[7];
    const float* a_gate  = (const float*)d_in[8];
    const float* a_up    = (const float*)d_in[9];
    const float* a_down  = (const float*)d_in[10];
    const float* a_ln1   = (const float*)d_in[11];
    const float* a_ln2   = (const float*)d_in[12];
    const float* conv_w  = (const float*)d_in[13];
    const float* conv_b  = (const float*)d_in[14];
    const float* in_w    = (const float*)d_in[15];
    const float* in_b    = (const float*)d_in[16];
    const float* out_w   = (const float*)d_in[17];
    const float* out_b   = (const float*)d_in[18];
    const float* c_gate  = (const float*)d_in[19];
    const float* c_up    = (const float*)d_in[20];
    const float* c_down  = (const float*)d_in[21];
    const float* c_ln1   = (const float*)d_in[22];
    const float* c_ln2   = (const float*)d_in[23];
    const float* finln   = (const float*)d_in[24];
    const float* lm_head = (const float*)d_in[25];

    cudaFuncSetAttribute(gemm_bf16x3<1>, cudaFuncAttributeMaxDynamicSharedMemorySize, SMEM_TM1);
    cudaFuncSetAttribute(gemm_bf16x3<2>, cudaFuncAttributeMaxDynamicSharedMemorySize, SMEM_TM2);

    float *x, *qkv, *t1, *t12;
    __nv_bfloat16 *ah, *al, *wh, *wl;
    cudaGetSymbolAddress((void**)&x,   g_x);
    cudaGetSymbolAddress((void**)&qkv, g_qkv);
    cudaGetSymbolAddress((void**)&t1,  g_t1);
    cudaGetSymbolAddress((void**)&t12, g_t12);
    cudaGetSymbolAddress((void**)&ah,  g_ah);
    cudaGetSymbolAddress((void**)&al,  g_al);
    cudaGetSymbolAddress((void**)&wh,  g_wh);
    cudaGetSymbolAddress((void**)&wl,  g_wl);

    // ---- plan A: layer-0 (conv ci=0) weights only ----
    PlanBuilder A;
    A.seg(in_w,   OFF_INW,  1769472);                       // in_w[0]
    A.seg(out_w,  OFF_OUTW, 589824);                        // out_w[0]
    A.seg(c_gate, OFF_CGU,           2359296);              // c_gate[0]
    A.seg(c_up,   OFF_CGU + 2359296, 2359296);              // c_up[0]
    A.seg(c_down, OFF_CD,   2359296);                       // c_down[0]
    A.finalize();

    // ---- plan B: everything else ----
    PlanBuilder B;
    for (int ai = 0; ai < 4; ai++) {
        unsigned long long d = OFF_QKV + (unsigned long long)ai * QKVN * Hdim;
        B.seg(qw + (size_t)ai * 589824, d,          589824);
        B.seg(kw + (size_t)ai * 196608, d + 589824, 196608);
        B.seg(vw + (size_t)ai * 196608, d + 786432, 196608);
    }
    B.seg(ow, OFF_OW, 2359296);
    for (int ai = 0; ai < 4; ai++) {
        unsigned long long d = OFF_AGU + (unsigned long long)ai * GUN * Hdim;
        B.seg(a_gate + (size_t)ai * 2359296, d,           2359296);
        B.seg(a_up   + (size_t)ai * 2359296, d + 2359296, 2359296);
    }
    B.seg(a_down, OFF_AD, 9437184);
    B.seg(in_w  + 1769472, OFF_INW  + 1769472, 14155776 - 1769472);   // in_w[1..7]
    B.seg(out_w + 589824,  OFF_OUTW + 589824,  4718592 - 589824);     // out_w[1..7]
    for (int ci = 1; ci < 8; ci++) {
        unsigned long long d = OFF_CGU + (unsigned long long)ci * GUN * Hdim;
        B.seg(c_gate + (size_t)ci * 2359296, d,           2359296);
        B.seg(c_up   + (size_t)ci * 2359296, d + 2359296, 2359296);
    }
    B.seg(c_down + 2359296, OFF_CD + 2359296, 18874368 - 2359296);    // c_down[1..7]
    B.seg(lm_head, OFF_LM, 38633472);
    B.finalize();

    // ---- fork: side stream splits plan B while main runs layer 0 ----
    cudaStream_t s2;
    cudaStreamCreateWithFlags(&s2, cudaStreamNonBlocking);
    cudaEvent_t e1, e2;
    cudaEventCreateWithFlags(&e1, cudaEventDisableTiming);
    cudaEventCreateWithFlags(&e2, cudaEventDisableTiming);

    embed_kernel<<<ROWS, 256>>>(tokens, embed, x);
    wsplit_all_kernel<<<(unsigned)((A.cum + 255) / 256), 256>>>(A.plan, wh, wl, A.cum);

    cudaEventRecord(e1, 0);
    cudaStreamWaitEvent(s2, e1, 0);
    wsplit_all_kernel<<<(unsigned)((B.cum + 255) / 256), 256, 0, s2>>>(B.plan, wh, wl, B.cum);
    cudaEventRecord(e2, s2);

    int ai = 0, ci = 0;
    for (int l = 0; l < 12; l++) {
        if (l == 1) cudaStreamWaitEvent(0, e2, 0);   // join side stream after layer 0
        bool full = (l == 2 || l == 5 || l == 8 || l == 11);
        if (full) {
            size_t oqkv = OFF_QKV + (size_t)ai * QKVN * Hdim;
            size_t oo   = OFF_OW  + (size_t)ai * Hdim * Hdim;
            size_t ogu  = OFF_AGU + (size_t)ai * GUN * Hdim;
            size_t od   = OFF_AD  + (size_t)ai * Hdim * IM;
            rmsnorm_split_kernel<<<ROWS, 256>>>(x, a_ln1 + (size_t)ai * Hdim, ah, al, Hdim);
            gemm(ah, al, wh + oqkv, wl + oqkv, qkv, ROWS, QKVN, Hdim, 0, 0);
            qknorm_rope_kernel<<<ROWS * 16 / 8, 256>>>(qkv, qln + (size_t)ai * HD, kln + (size_t)ai * HD);
            attn_kernel<<<BATCH * NH * SEQ / 8, 256>>>(qkv, ah, al);
            gemm(ah, al, wh + oo, wl + oo, x, ROWS, Hdim, Hdim, 0, x);
            rmsnorm_split_kernel<<<ROWS, 256>>>(x, a_ln2 + (size_t)ai * Hdim, ah, al, Hdim);
            gemm(ah, al, wh + ogu, wl + ogu, t12, ROWS, GUN, Hdim, 0, 0);
            silu_mul_split_kernel<<<(ROWS * IM / 4) / 256, 256>>>(t12, ah, al);
            gemm(ah, al, wh + od, wl + od, x, ROWS, Hdim, IM, 0, x);
            ai++;
        } else {
            size_t oi  = OFF_INW  + (size_t)ci * H3 * Hdim;
            size_t oo  = OFF_OUTW + (size_t)ci * Hdim * Hdim;
            size_t ogu = OFF_CGU  + (size_t)ci * GUN * Hdim;
            size_t od  = OFF_CD   + (size_t)ci * Hdim * IM;
            rmsnorm_split_kernel<<<ROWS, 256>>>(x, c_ln1 + (size_t)ci * Hdim, ah, al, Hdim);
            gemm(ah, al, wh + oi, wl + oi, t1, ROWS, H3, Hdim, in_b + (size_t)ci * H3, 0);
            conv_split_kernel<<<(ROWS * Hdim) / 256, 256>>>(t1, conv_w + (size_t)ci * Hdim * KCONV,
                                                            conv_b + (size_t)ci * Hdim, ah, al);
            gemm(ah, al, wh + oo, wl + oo, x, ROWS, Hdim, Hdim, out_b + (size_t)ci * Hdim, x);
            rmsnorm_split_kernel<<<ROWS, 256>>>(x, c_ln2 + (size_t)ci * Hdim, ah, al, Hdim);
            gemm(ah, al, wh + ogu, wl + ogu, t12, ROWS, GUN, Hdim, 0, 0);
            silu_mul_split_kernel<<<(ROWS * IM / 4) / 256, 256>>>(t12, ah, al);
            gemm(ah, al, wh + od, wl + od, x, ROWS, Hdim, IM, 0, x);
            ci++;
        }
    }
    rmsnorm_split_kernel<<<ROWS, 256>>>(x, finln, ah, al, Hdim);
    gemm(ah, al, wh + OFF_LM, wl + OFF_LM, (float*)d_out, ROWS, VOCAB, Hdim, 0, 0);

    cudaEventDestroy(e1);
    cudaEventDestroy(e2);
    cudaStreamDestroy(s2);
}

// round 17
// speedup vs baseline: 2.4285x; 1.0442x over previous
#include <cuda_runtime.h>
#include <cuda_bf16.h>
#include <cuda_fp16.h>
#include <math.h>
#include <stdint.h>

// ---------------- constants ----------------
#define Hdim 768
#define NH 12
#define NKV 4
#define HD 64
#define IM 3072
#define KCONV 4
#define SEQ 1024
#define BATCH 2
#define ROWS (BATCH*SEQ)      // 2048
#define VOCAB 50304
#define H3 (3*Hdim)           // 2304
#define QKVN 1280             // 768 + 256 + 256
#define GUN  (2*IM)           // 6144

#define BK 32
#define NST 3

// ---------------- packed weight offsets (elems) ----------------
#define OFF_QKV  0ull
#define OFF_OW   3932160ull
#define OFF_AGU  6291456ull
#define OFF_AD   25165824ull
#define OFF_INW  34603008ull
#define OFF_OUTW 48758784ull
#define OFF_CGU  53477376ull
#define OFF_CD   91226112ull
#define OFF_LM   110100480ull
#define W_TOTAL  148733952ull

// ---------------- scratch ----------------
__device__ float g_x  [ROWS*Hdim];
__device__ float g_qkv[ROWS*QKVN];
__device__ float g_t1 [ROWS*H3];
__device__ float g_t12[ROWS*GUN];
__device__ __nv_bfloat16 g_ah[ROWS*IM];
__device__ __nv_bfloat16 g_al[ROWS*IM];
__device__ __nv_bfloat16 g_wh[W_TOTAL];
__device__ __nv_bfloat16 g_wl[W_TOTAL];

// ---------------- helpers ----------------
__device__ __forceinline__ void split1(float x, __nv_bfloat16* h, __nv_bfloat16* l) {
    __nv_bfloat16 hh = __float2bfloat16(x);
    *h = hh;
    *l = __float2bfloat16(x - __bfloat162float(hh));
}
__device__ __forceinline__ void split1h(float x, unsigned short* h, unsigned short* l) {
    __half hh = __float2half(x);
    __half ll = __float2half(x - __half2float(hh));
    *h = __half_as_ushort(hh);
    *l = __half_as_ushort(ll);
}
__device__ __forceinline__ unsigned cvta_s(const void* p) {
    return (unsigned)__cvta_generic_to_shared(p);
}
__device__ __forceinline__ void cp16(unsigned saddr, const void* g) {
    asm volatile("cp.async.cg.shared.global [%0], [%1], 16;\n" :: "r"(saddr), "l"(g));
}
__device__ __forceinline__ void ldm4(unsigned* r, unsigned addr) {
    asm volatile("ldmatrix.sync.aligned.m8n8.x4.shared.b16 {%0,%1,%2,%3}, [%4];\n"
                 : "=r"(r[0]), "=r"(r[1]), "=r"(r[2]), "=r"(r[3]) : "r"(addr));
}
__device__ __forceinline__ void mma16816(float* d, const unsigned* a, const unsigned* b) {
    asm volatile("mma.sync.aligned.m16n8k16.row.col.f32.bf16.bf16.f32 "
                 "{%0,%1,%2,%3}, {%4,%5,%6,%7}, {%8,%9}, {%0,%1,%2,%3};\n"
                 : "+f"(d[0]), "+f"(d[1]), "+f"(d[2]), "+f"(d[3])
                 : "r"(a[0]), "r"(a[1]), "r"(a[2]), "r"(a[3]), "r"(b[0]), "r"(b[1]));
}
__device__ __forceinline__ void mma16816h(float* d, const unsigned* a, const unsigned* b) {
    asm volatile("mma.sync.aligned.m16n8k16.row.col.f32.f16.f16.f32 "
                 "{%0,%1,%2,%3}, {%4,%5,%6,%7}, {%8,%9}, {%0,%1,%2,%3};\n"
                 : "+f"(d[0]), "+f"(d[1]), "+f"(d[2]), "+f"(d[3])
                 : "r"(a[0]), "r"(a[1]), "r"(a[2]), "r"(a[3]), "r"(b[0]), "r"(b[1]));
}
__device__ __forceinline__ unsigned sw_addr(unsigned base, int row, int col) {
    int u = col >> 3;
    return base + row * 64 + ((u ^ ((row >> 1) & 3)) << 4);
}

// ================= bf16x3 split GEMM (unchanged, proven) =================
template<int TM>
__global__ void __launch_bounds__(256, 3 - TM) gemm_bf16x3(
    const __nv_bfloat16* __restrict__ Ah, const __nv_bfloat16* __restrict__ Al,
    const __nv_bfloat16* __restrict__ Bh, const __nv_bfloat16* __restrict__ Bl,
    float* __restrict__ C, int M, int N, int K,
    const float* __restrict__ bias, const float* __restrict__ res)
{
    constexpr int MR      = 64 * TM;
    constexpr int ARR_A   = MR * 64;
    constexpr int ARR_Bb  = 8192;
    constexpr int STAGE   = 2 * ARR_A + 2 * ARR_Bb;
    constexpr int ALD     = MR * 8;
    constexpr int NLDIT   = (ALD + 1024) / 256;

    extern __shared__ __align__(16) char sm_raw[];
    const int tid = threadIdx.x;
    const int lane = tid & 31, wid = tid >> 5;
    const int wm = wid >> 1, wn = wid & 1;
    const int bm = blockIdx.x * MR, bn = blockIdx.y * 128;
    const unsigned sbase = cvta_s(sm_raw);

    const __nv_bfloat16* gpA[2] = { Ah + (size_t)bm * K, Al + (size_t)bm * K };
    const __nv_bfloat16* gpB[2] = { Bh + (size_t)bn * K, Bl + (size_t)bn * K };

    float acc[TM][8][4];
    #pragma unroll
    for (int t = 0; t < TM; t++)
        #pragma unroll
        for (int n = 0; n < 8; n++)
            #pragma unroll
            for (int i = 0; i < 4; i++) acc[t][n][i] = 0.f;

    auto load_chunk = [&](int st, int c) {
        int gk = c * BK;
        unsigned sb = sbase + st * STAGE;
        #pragma unroll
        for (int i = 0; i < NLDIT; i++) {
            int idx = tid + i * 256;
            if (idx < ALD) {
                int arr = idx / (MR * 4);
                int j = idx - arr * (MR * 4);
                int r = j >> 2, u = j & 3;
                unsigned sa = sb + arr * ARR_A + r * 64 + ((u ^ ((r >> 1) & 3)) << 4);
                cp16(sa, gpA[arr] + (size_t)r * K + gk + u * 8);
            } else {
                int x = idx - ALD;
                int arr = x >> 9;
                int j = x & 511;
                int r = j >> 2, u = j & 3;
                unsigned sa = sb + 2 * ARR_A + arr * ARR_Bb + r * 64 + ((u ^ ((r >> 1) & 3)) << 4);
                cp16(sa, gpB[arr] + (size_t)r * K + gk + u * 8);
            }
        }
        asm volatile("cp.async.commit_group;\n");
    };

    const int KT = K / BK;
    load_chunk(0, 0);
    load_chunk(1, 1);

    for (int c = 0; c < KT; c++) {
        if (c + 1 < KT) asm volatile("cp.async.wait_group 1;\n");
        else            asm volatile("cp.async.wait_group 0;\n");
        __syncthreads();
        if (c + 2 < KT) load_chunk((c + 2) % NST, c + 2);

        unsigned st = sbase + (c % NST) * STAGE;
        #pragma unroll
        for (int kk = 0; kk < BK; kk += 16) {
            unsigned ah[TM][4], al[TM][4], bh[8][2], bl[8][2];
            #pragma unroll
            for (int t = 0; t < TM; t++) {
                int row = wm * (16 * TM) + t * 16 + (lane & 15);
                int col = kk + ((lane >> 4) << 3);
                ldm4(ah[t], sw_addr(st,          row, col));
                ldm4(al[t], sw_addr(st + ARR_A,  row, col));
            }
            #pragma unroll
            for (int p = 0; p < 4; p++) {
                int m = lane >> 3;
                int row = wn * 64 + p * 16 + ((m >> 1) << 3) + (lane & 7);
                int col = kk + ((m & 1) << 3);
                unsigned r[4];
                ldm4(r, sw_addr(st + 2 * ARR_A,           row, col));
                bh[2 * p][0] = r[0]; bh[2 * p][1] = r[1];
                bh[2 * p + 1][0] = r[2]; bh[2 * p + 1][1] = r[3];
                ldm4(r, sw_addr(st + 2 * ARR_A + ARR_Bb,  row, col));
                bl[2 * p][0] = r[0]; bl[2 * p][1] = r[1];
                bl[2 * p + 1][0] = r[2]; bl[2 * p + 1][1] = r[3];
            }
            #pragma unroll
            for (int t = 0; t < TM; t++)
                #pragma unroll
                for (int n = 0; n < 8; n++) {
                    mma16816(acc[t][n], ah[t], bh[n]);
                    mma16816(acc[t][n], ah[t], bl[n]);
                    mma16816(acc[t][n], al[t], bh[n]);
                }
        }
    }

    #pragma unroll
    for (int t = 0; t < TM; t++) {
        int row0 = bm + wm * (16 * TM) + t * 16 + (lane >> 2);
        #pragma unroll
        for (int n = 0; n < 8; n++) {
            int col = bn + wn * 64 + n * 8 + (lane & 3) * 2;
            #pragma unroll
            for (int hh = 0; hh < 2; hh++) {
                int row = row0 + hh * 8;
                float v0 = acc[t][n][hh * 2], v1 = acc[t][n][hh * 2 + 1];
                if (bias) { v0 += bias[col]; v1 += bias[col + 1]; }
                if (res) {
                    const float* rp = res + (size_t)row * N + col;
                    v0 += rp[0]; v1 += rp[1];
                }
                *(float2*)(C + (size_t)row * N + col) = make_float2(v0, v1);
            }
        }
    }
}

#define SMEM_TM2 (NST * (2*8192 + 2*8192))   // 98304
#define SMEM_TM1 (NST * (2*4096 + 2*8192))   // 73728

// ================= fp16 2-term GEMM (LM head): C = Ah*(Bh+Bl)^T =================
// 128x128 tile, A fp16 single array, B fp16 hi/lo. grid = (M/128, N/128).
__global__ void __launch_bounds__(256) gemm_f16x2(
    const unsigned short* __restrict__ Ah,
    const unsigned short* __restrict__ Bh, const unsigned short* __restrict__ Bl,
    float* __restrict__ C, int M, int N, int K)
{
    constexpr int ARR_A  = 8192;               // 128 rows x 32 fp16
    constexpr int ARR_Bb = 8192;
    constexpr int STAGE  = ARR_A + 2 * ARR_Bb; // 24576
    extern __shared__ __align__(16) char sm_raw[];
    const int tid = threadIdx.x;
    const int lane = tid & 31, wid = tid >> 5;
    const int wm = wid >> 1, wn = wid & 1;
    const int bm = blockIdx.x * 128, bn = blockIdx.y * 128;
    const unsigned sbase = cvta_s(sm_raw);

    const unsigned short* gA = Ah + (size_t)bm * K;
    const unsigned short* gpB[2] = { Bh + (size_t)bn * K, Bl + (size_t)bn * K };

    float acc[2][8][4];
    #pragma unroll
    for (int t = 0; t < 2; t++)
        #pragma unroll
        for (int n = 0; n < 8; n++)
            #pragma unroll
            for (int i = 0; i < 4; i++) acc[t][n][i] = 0.f;

    auto load_chunk = [&](int st, int c) {
        int gk = c * BK;
        unsigned sb = sbase + st * STAGE;
        #pragma unroll
        for (int i = 0; i < 6; i++) {          // 1536 16B-units
            int idx = tid + i * 256;
            if (idx < 512) {
                int r = idx >> 2, u = idx & 3;
                unsigned sa = sb + r * 64 + ((u ^ ((r >> 1) & 3)) << 4);
                cp16(sa, gA + (size_t)r * K + gk + u * 8);
            } else {
                int x = idx - 512;
                int arr = x >> 9;
                int j = x & 511;
                int r = j >> 2, u = j & 3;
                unsigned sa = sb + ARR_A + arr * ARR_Bb + r * 64 + ((u ^ ((r >> 1) & 3)) << 4);
                cp16(sa, gpB[arr] + (size_t)r * K + gk + u * 8);
            }
        }
        asm volatile("cp.async.commit_group;\n");
    };

    const int KT = K / BK;
    load_chunk(0, 0);
    load_chunk(1, 1);

    for (int c = 0; c < KT; c++) {
        if (c + 1 < KT) asm volatile("cp.async.wait_group 1;\n");
        else            asm volatile("cp.async.wait_group 0;\n");
        __syncthreads();
        if (c + 2 < KT) load_chunk((c + 2) % NST, c + 2);

        unsigned st = sbase + (c % NST) * STAGE;
        #pragma unroll
        for (int kk = 0; kk < BK; kk += 16) {
            unsigned ah[2][4], bh[8][2], bl[8][2];
            #pragma unroll
            for (int t = 0; t < 2; t++) {
                int row = wm * 32 + t * 16 + (lane & 15);
                int col = kk + ((lane >> 4) << 3);
                ldm4(ah[t], sw_addr(st, row, col));
            }
            #pragma unroll
            for (int p = 0; p < 4; p++) {
                int m = lane >> 3;
                int row = wn * 64 + p * 16 + ((m >> 1) << 3) + (lane & 7);
                int col = kk + ((m & 1) << 3);
                unsigned r[4];
                ldm4(r, sw_addr(st + ARR_A,          row, col));
                bh[2 * p][0] = r[0]; bh[2 * p][1] = r[1];
                bh[2 * p + 1][0] = r[2]; bh[2 * p + 1][1] = r[3];
                ldm4(r, sw_addr(st + ARR_A + ARR_Bb, row, col));
                bl[2 * p][0] = r[0]; bl[2 * p][1] = r[1];
                bl[2 * p + 1][0] = r[2]; bl[2 * p + 1][1] = r[3];
            }
            #pragma unroll
            for (int t = 0; t < 2; t++)
                #pragma unroll
                for (int n = 0; n < 8; n++) {
                    mma16816h(acc[t][n], ah[t], bh[n]);
                    mma16816h(acc[t][n], ah[t], bl[n]);
                }
        }
    }

    #pragma unroll
    for (int t = 0; t < 2; t++) {
        int row0 = bm + wm * 32 + t * 16 + (lane >> 2);
        #pragma unroll
        for (int n = 0; n < 8; n++) {
            int col = bn + wn * 64 + n * 8 + (lane & 3) * 2;
            #pragma unroll
            for (int hh = 0; hh < 2; hh++) {
                int row = row0 + hh * 8;
                *(float2*)(C + (size_t)row * N + col) =
                    make_float2(acc[t][n][hh * 2], acc[t][n][hh * 2 + 1]);
            }
        }
    }
}
#define SMEM_F16 (NST * 24576)   // 73728

// ---------------- fused weight-split kernel (32B/thread, per-seg dtype) ----------------
#define NSEG 42
struct WSeg { const float4* src; long long dst8; long long end8; int h16; int pad; };
struct WPlan { WSeg s[NSEG]; };

__global__ void wsplit_all_kernel(WPlan p, __nv_bfloat16* __restrict__ H,
                                  __nv_bfloat16* __restrict__ L, long long total8) {
    long long idx = (long long)blockIdx.x * 256 + threadIdx.x;
    if (idx >= total8) return;
    int lo = 0, hi = NSEG - 1;
    while (lo < hi) { int mid = (lo + hi) >> 1; if (idx < p.s[mid].end8) hi = mid; else lo = mid + 1; }
    long long start = lo ? p.s[lo - 1].end8 : 0;
    long long off = idx - start;
    const float4* sp = p.s[lo].src + off * 2;
    float4 v0 = sp[0], v1 = sp[1];
    float vv[8] = { v0.x, v0.y, v0.z, v0.w, v1.x, v1.y, v1.z, v1.w };
    unsigned short h[8], l[8];
    if (p.s[lo].h16) {
        #pragma unroll
        for (int i = 0; i < 8; i++) split1h(vv[i], &h[i], &l[i]);
    } else {
        #pragma unroll
        for (int i = 0; i < 8; i++)
            split1(vv[i], (__nv_bfloat16*)&h[i], (__nv_bfloat16*)&l[i]);
    }
    long long d = p.s[lo].dst8 + off;
    *(uint4*)(H + d * 8) = *(uint4*)h;
    *(uint4*)(L + d * 8) = *(uint4*)l;
}

// ---------------- embedding gather ----------------
__global__ void embed_kernel(const int* __restrict__ tok, const float* __restrict__ E,
                             float* __restrict__ X) {
    int row = blockIdx.x;
    int t = tok[row];
    const float* src = E + (size_t)t * Hdim;
    float* dst = X + (size_t)row * Hdim;
    for (int c = threadIdx.x; c < Hdim; c += blockDim.x) dst[c] = src[c];
}

// ---------------- rmsnorm -> 16-bit hi/lo, vectorized (192 thr, n=768) ----------------
// mode 0: bf16 hi/lo split; mode 1: fp16 hi only (for fp16 2-term LM GEMM)
__global__ void __launch_bounds__(192) rmsnorm_split_kernel(
    const float* __restrict__ X, const float* __restrict__ W,
    __nv_bfloat16* __restrict__ Hh, __nv_bfloat16* __restrict__ Hl, int mode) {
    int row = blockIdx.x;
    int tid = threadIdx.x;
    const float4 v = ((const float4*)(X + (size_t)row * Hdim))[tid];
    float s = v.x * v.x + v.y * v.y + v.z * v.z + v.w * v.w;
    __shared__ float sm[8];
    #pragma unroll
    for (int o = 16; o; o >>= 1) s += __shfl_xor_sync(~0u, s, o);
    if ((tid & 31) == 0) sm[tid >> 5] = s;
    __syncthreads();
    if (tid < 32) {
        float t = (tid < 6) ? sm[tid] : 0.f;
        #pragma unroll
        for (int o = 4; o; o >>= 1) t += __shfl_xor_sync(~0u, t, o);
        if (tid == 0) sm[0] = t;
    }
    __syncthreads();
    float r = rsqrtf(sm[0] * (1.0f / Hdim) + 1e-6f);
    const float4 w = ((const float4*)W)[tid];
    float y[4] = { v.x * r * w.x, v.y * r * w.y, v.z * r * w.z, v.w * r * w.w };
    unsigned short h[4], l[4];
    if (mode) {
        #pragma unroll
        for (int i = 0; i < 4; i++) h[i] = __half_as_ushort(__float2half(y[i]));
        *(uint2*)(Hh + (size_t)row * Hdim + tid * 4) = *(uint2*)h;
    } else {
        #pragma unroll
        for (int i = 0; i < 4; i++)
            split1(y[i], (__nv_bfloat16*)&h[i], (__nv_bfloat16*)&l[i]);
        *(uint2*)(Hh + (size_t)row * Hdim + tid * 4) = *(uint2*)h;
        *(uint2*)(Hl + (size_t)row * Hdim + tid * 4) = *(uint2*)l;
    }
}

// ---------------- per-head RMSNorm (q/k) + RoPE on fused QKV buffer ----------------
__global__ void qknorm_rope_kernel(float* __restrict__ QKV,
                                   const float* __restrict__ qln, const float* __restrict__ kln) {
    int w = threadIdx.x >> 5, l = threadIdx.x & 31;
    int g = blockIdx.x * 8 + w;
    int hh = g & 15;
    int row = g >> 4;
    int s = row & (SEQ - 1);
    float* p; const float* wn;
    if (hh < NH) { p = QKV + (size_t)row * QKVN + hh * HD;               wn = qln; }
    else         { p = QKV + (size_t)row * QKVN + 768 + (hh - NH) * HD;  wn = kln; }
    float a = p[l], b = p[l + 32];
    float ss = a * a + b * b;
    #pragma unroll
    for (int o = 16; o; o >>= 1) ss += __shfl_xor_sync(~0u, ss, o);
    float r = rsqrtf(ss * (1.0f / HD) + 1e-6f);
    a *= r * wn[l];
    b *= r * wn[l + 32];
    float inv = powf(10000.0f, -((float)l) / 32.0f);
    float ang = (float)s * inv;
    float cs = cosf(ang), sn = sinf(ang);
    p[l]      = a * cs - b * sn;
    p[l + 32] = b * cs + a * sn;
}

// ---------------- causal attention V2: smem K/V tiles ----------------
#define KTILE 128
#define KVP 68
__global__ void __launch_bounds__(256) attn_kernel(
    const float* __restrict__ QKV,
    __nv_bfloat16* __restrict__ Oh, __nv_bfloat16* __restrict__ Ol) {
    __shared__ float qs[8][HD];
    __shared__ float sc[8][SEQ];
    __shared__ float kv[KTILE][KVP];
    int w = threadIdx.x >> 5, l = threadIdx.x & 31;
    int g = blockIdx.x * 8 + w;
    int s = g & (SEQ - 1);
    int bh = g >> 10;
    int h = bh % NH, b = bh / NH;
    int kvh = h / (NH / NKV);
    int s0 = (blockIdx.x * 8) & (SEQ - 1);
    int smax = s0 + 7;
    int ntile = smax / KTILE + 1;

    const float* qp = QKV + (size_t)(b * SEQ + s) * QKVN + h * HD;
    qs[w][l] = qp[l]; qs[w][l + 32] = qp[l + 32];
    __syncwarp();
    const float* Kb = QKV + (size_t)b * SEQ * QKVN + 768 + kvh * HD;
    const float* Vb = QKV + (size_t)b * SEQ * QKVN + 1024 + kvh * HD;

    for (int jt = 0; jt < ntile; jt++) {
        __syncthreads();
        for (int i = threadIdx.x; i < KTILE * 16; i += 256) {
            int key = i >> 4, d4 = i & 15;
            *(float4*)&kv[key][d4 * 4] =
                *(const float4*)(Kb + (size_t)(jt * KTILE + key) * QKVN + d4 * 4);
        }
        __syncthreads();
        int jend = jt * KTILE + KTILE - 1; if (jend > s) jend = s;
        for (int j = jt * KTILE + l; j <= jend; j += 32) {
            const float* kr = kv[j - jt * KTILE];
            float d = 0.f;
            #pragma unroll
            for (int i = 0; i < 16; i++) {
                float4 kk = *(const float4*)&kr[4 * i];
                d += qs[w][4*i] * kk.x + qs[w][4*i+1] * kk.y + qs[w][4*i+2] * kk.z + qs[w][4*i+3] * kk.w;
            }
            sc[w][j] = d * 0.125f;
        }
    }
    __syncwarp();
    float m = -1e30f;
    for (int j = l; j <= s; j += 32) m = fmaxf(m, sc[w][j]);
    #pragma unroll
    for (int o = 16; o; o >>= 1) m = fmaxf(m, __shfl_xor_sync(~0u, m, o));
    float sum = 0.f;
    for (int j = l; j <= s; j += 32) { float p = expf(sc[w][j] - m); sc[w][j] = p; sum += p; }
    #pragma unroll
    for (int o = 16; o; o >>= 1) sum += __shfl_xor_sync(~0u, sum, o);
    __syncwarp();
    float oa = 0.f, ob = 0.f;
    for (int jt = 0; jt < ntile; jt++) {
        __syncthreads();
        for (int i = threadIdx.x; i < KTILE * 16; i += 256) {
            int key = i >> 4, d4 = i & 15;
            *(float4*)&kv[key][d4 * 4] =
                *(const float4*)(Vb + (size_t)(jt * KTILE + key) * QKVN + d4 * 4);
        }
        __syncthreads();
        int jend = jt * KTILE + KTILE - 1; if (jend > s) jend = s;
        for (int j = jt * KTILE; j <= jend; j++) {
            float p = sc[w][j];
            const float* vr = kv[j - jt * KTILE];
            oa += p * vr[l]; ob += p * vr[l + 32];
        }
    }
    float invs = 1.0f / sum;
    size_t op = ((size_t)(b * SEQ + s) * NH + h) * HD;
    split1(oa * invs, &Oh[op + l], &Ol[op + l]);
    split1(ob * invs, &Oh[op + l + 32], &Ol[op + l + 32]);
}

// ---------------- causal depthwise conv -> bf16 hi/lo ----------------
__global__ void conv_split_kernel(const float* __restrict__ T, const float* __restrict__ W4,
                                  const float* __restrict__ cb,
                                  __nv_bfloat16* __restrict__ Yh, __nv_bfloat16* __restrict__ Yl) {
    int idx = blockIdx.x * blockDim.x + threadIdx.x;
    int c = idx % Hdim;
    int row = idx / Hdim;
    int s = row & (SEQ - 1);
    int b = row / SEQ;
    const float* w = W4 + (size_t)c * KCONV;
    float acc = cb[c];
    #pragma unroll
    for (int j = 0; j < KCONV; j++) {
        int sp = s - (KCONV - 1) + j;
        if (sp >= 0) {
            const float* tr = T + (size_t)(b * SEQ + sp) * H3;
            acc += w[j] * tr[c] * tr[2 * Hdim + c];
        }
    }
    float Cg = T[(size_t)row * H3 + Hdim + c];
    split1(Cg * acc, &Yh[(size_t)row * Hdim + c], &Yl[(size_t)row * Hdim + c]);
}

// ---------------- silu(gate)*up, vectorized x4 -> bf16 hi/lo ----------------
__global__ void silu_mul_split_kernel(const float* __restrict__ T,
                                      __nv_bfloat16* __restrict__ Hh, __nv_bfloat16* __restrict__ Hl) {
    int idx = blockIdx.x * blockDim.x + threadIdx.x;   // over ROWS*IM/4
    int row = idx / (IM / 4), c4 = idx - row * (IM / 4);
    const float4 g4 = *(const float4*)(T + (size_t)row * GUN + c4 * 4);
    const float4 u4 = *(const float4*)(T + (size_t)row * GUN + IM + c4 * 4);
    float gg[4] = { g4.x, g4.y, g4.z, g4.w };
    float uu[4] = { u4.x, u4.y, u4.z, u4.w };
    __nv_bfloat16 h[4], l[4];
    #pragma unroll
    for (int i = 0; i < 4; i++) {
        float g = gg[i];
        float y = (g / (1.0f + expf(-g))) * uu[i];
        split1(y, &h[i], &l[i]);
    }
    size_t d = (size_t)row * IM + c4 * 4;
    *(uint2*)(Hh + d) = *(uint2*)h;
    *(uint2*)(Hl + d) = *(uint2*)l;
}

// ---------------- host-side plumbing ----------------
static void gemm(const __nv_bfloat16* Ah, const __nv_bfloat16* Al,
                 const __nv_bfloat16* Bh, const __nv_bfloat16* Bl,
                 float* C, int M, int N, int K, const float* bias, const float* res) {
    if (N <= 1280) {
        dim3 grid(M / 64, N / 128);
        gemm_bf16x3<1><<<grid, 256, SMEM_TM1>>>(Ah, Al, Bh, Bl, C, M, N, K, bias, res);
    } else {
        dim3 grid(M / 128, N / 128);
        gemm_bf16x3<2><<<grid, 256, SMEM_TM2>>>(Ah, Al, Bh, Bl, C, M, N, K, bias, res);
    }
}

struct PlanBuilder {
    WPlan plan;
    long long cum = 0;
    int si = 0;
    void seg(const float* src, unsigned long long dst_elems, long long n_elems, int h16 = 0) {
        plan.s[si].src  = (const float4*)src;
        plan.s[si].dst8 = (long long)(dst_elems / 8);
        plan.s[si].h16  = h16;
        plan.s[si].pad  = 0;
        cum += n_elems / 8;
        plan.s[si].end8 = cum;
        si++;
    }
    void finalize() {
        for (int i = si; i < NSEG; i++) {
            plan.s[i].src = nullptr;
            plan.s[i].dst8 = 0;
            plan.s[i].h16 = 0;
            plan.s[i].pad = 0;
            plan.s[i].end8 = cum;
        }
    }
};

extern "C" void kernel_launch(void* const* d_in, const int* in_sizes, int n_in,
                              void* d_out, int out_size) {
    const int*   tokens  = (const int*)  d_in[0];
    const float* embed   = (const float*)d_in[1];
    const float* qw      = (const float*)d_in[2];
    const float* kw      = (const float*)d_in[3];
    const float* vw      = (const float*)d_in[4];
    const float* ow      = (const float*)d_in[5];
    const float* qln     = (const float*)d_in[6];
    const float* kln     = (const float*)d_in[7];
    const float* a_gate  = (const float*)d_in[8];
    const float* a_up    = (const float*)d_in[9];
    const float* a_down  = (const float*)d_in[10];
    const float* a_ln1   = (const float*)d_in[11];
    const float* a_ln2   = (const float*)d_in[12];
    const float* conv_w  = (const float*)d_in[13];
    const float* conv_b  = (const float*)d_in[14];
    const float* in_w    = (const float*)d_in[15];
    const float* in_b    = (const float*)d_in[16];
    const float* out_w   = (const float*)d_in[17];
    const float* out_b   = (const float*)d_in[18];
    const float* c_gate  = (const float*)d_in[19];
    const float* c_up    = (const float*)d_in[20];
    const float* c_down  = (const float*)d_in[21];
    const float* c_ln1   = (const float*)d_in[22];
    const float* c_ln2   = (const float*)d_in[23];
    const float* finln   = (const float*)d_in[24];
    const float* lm_head = (const float*)d_in[25];

    cudaFuncSetAttribute(gemm_bf16x3<1>, cudaFuncAttributeMaxDynamicSharedMemorySize, SMEM_TM1);
    cudaFuncSetAttribute(gemm_bf16x3<2>, cudaFuncAttributeMaxDynamicSharedMemorySize, SMEM_TM2);
    cudaFuncSetAttribute(gemm_f16x2,     cudaFuncAttributeMaxDynamicSharedMemorySize, SMEM_F16);

    float *x, *qkv, *t1, *t12;
    __nv_bfloat16 *ah, *al, *wh, *wl;
    cudaGetSymbolAddress((void**)&x,   g_x);
    cudaGetSymbolAddress((void**)&qkv, g_qkv);
    cudaGetSymbolAddress((void**)&t1,  g_t1);
    cudaGetSymbolAddress((void**)&t12, g_t12);
    cudaGetSymbolAddress((void**)&ah,  g_ah);
    cudaGetSymbolAddress((void**)&al,  g_al);
    cudaGetSymbolAddress((void**)&wh,  g_wh);
    cudaGetSymbolAddress((void**)&wl,  g_wl);

    // ---- plan A: layer-0 (conv ci=0) weights only ----
    PlanBuilder A;
    A.seg(in_w,   OFF_INW,  1769472);
    A.seg(out_w,  OFF_OUTW, 589824);
    A.seg(c_gate, OFF_CGU,           2359296);
    A.seg(c_up,   OFF_CGU + 2359296, 2359296);
    A.seg(c_down, OFF_CD,   2359296);
    A.finalize();

    // ---- plan B: everything else (LM head as fp16 split) ----
    PlanBuilder B;
    for (int ai = 0; ai < 4; ai++) {
        unsigned long long d = OFF_QKV + (unsigned long long)ai * QKVN * Hdim;
        B.seg(qw + (size_t)ai * 589824, d,          589824);
        B.seg(kw + (size_t)ai * 196608, d + 589824, 196608);
        B.seg(vw + (size_t)ai * 196608, d + 786432, 196608);
    }
    B.seg(ow, OFF_OW, 2359296);
    for (int ai = 0; ai < 4; ai++) {
        unsigned long long d = OFF_AGU + (unsigned long long)ai * GUN * Hdim;
        B.seg(a_gate + (size_t)ai * 2359296, d,           2359296);
        B.seg(a_up   + (size_t)ai * 2359296, d + 2359296, 2359296);
    }
    B.seg(a_down, OFF_AD, 9437184);
    B.seg(in_w  + 1769472, OFF_INW  + 1769472, 14155776 - 1769472);
    B.seg(out_w + 589824,  OFF_OUTW + 589824,  4718592 - 589824);
    for (int ci = 1; ci < 8; ci++) {
        unsigned long long d = OFF_CGU + (unsigned long long)ci * GUN * Hdim;
        B.seg(c_gate + (size_t)ci * 2359296, d,           2359296);
        B.seg(c_up   + (size_t)ci * 2359296, d + 2359296, 2359296);
    }
    B.seg(c_down + 2359296, OFF_CD + 2359296, 18874368 - 2359296);
    B.seg(lm_head, OFF_LM, 38633472, /*h16=*/1);
    B.finalize();

    // ---- fork: side stream splits plan B while main runs layer 0 ----
    cudaStream_t s2;
    cudaStreamCreateWithFlags(&s2, cudaStreamNonBlocking);
    cudaEvent_t e1, e2;
    cudaEventCreateWithFlags(&e1, cudaEventDisableTiming);
    cudaEventCreateWithFlags(&e2, cudaEventDisableTiming);

    embed_kernel<<<ROWS, 256>>>(tokens, embed, x);
    wsplit_all_kernel<<<(unsigned)((A.cum + 255) / 256), 256>>>(A.plan, wh, wl, A.cum);

    cudaEventRecord(e1, 0);
    cudaStreamWaitEvent(s2, e1, 0);
    wsplit_all_kernel<<<(unsigned)((B.cum + 255) / 256), 256, 0, s2>>>(B.plan, wh, wl, B.cum);
    cudaEventRecord(e2, s2);

    int ai = 0, ci = 0;
    for (int l = 0; l < 12; l++) {
        if (l == 1) cudaStreamWaitEvent(0, e2, 0);
        bool full = (l == 2 || l == 5 || l == 8 || l == 11);
        if (full) {
            size_t oqkv = OFF_QKV + (size_t)ai * QKVN * Hdim;
            size_t oo   = OFF_OW  + (size_t)ai * Hdim * Hdim;
            size_t ogu  = OFF_AGU + (size_t)ai * GUN * Hdim;
            size_t od   = OFF_AD  + (size_t)ai * Hdim * IM;
            rmsnorm_split_kernel<<<ROWS, 192>>>(x, a_ln1 + (size_t)ai * Hdim, ah, al, 0);
            gemm(ah, al, wh + oqkv, wl + oqkv, qkv, ROWS, QKVN, Hdim, 0, 0);
            qknorm_rope_kernel<<<ROWS * 16 / 8, 256>>>(qkv, qln + (size_t)ai * HD, kln + (size_t)ai * HD);
            attn_kernel<<<BATCH * NH * SEQ / 8, 256>>>(qkv, ah, al);
            gemm(ah, al, wh + oo, wl + oo, x, ROWS, Hdim, Hdim, 0, x);
            rmsnorm_split_kernel<<<ROWS, 192>>>(x, a_ln2 + (size_t)ai * Hdim, ah, al, 0);
            gemm(ah, al, wh + ogu, wl + ogu, t12, ROWS, GUN, Hdim, 0, 0);
            silu_mul_split_kernel<<<(ROWS * IM / 4) / 256, 256>>>(t12, ah, al);
            gemm(ah, al, wh + od, wl + od, x, ROWS, Hdim, IM, 0, x);
            ai++;
        } else {
            size_t oi  = OFF_INW  + (size_t)ci * H3 * Hdim;
            size_t oo  = OFF_OUTW + (size_t)ci * Hdim * Hdim;
            size_t ogu = OFF_CGU  + (size_t)ci * GUN * Hdim;
            size_t od  = OFF_CD   + (size_t)ci * Hdim * IM;
            rmsnorm_split_kernel<<<ROWS, 192>>>(x, c_ln1 + (size_t)ci * Hdim, ah, al, 0);
            gemm(ah, al, wh + oi, wl + oi, t1, ROWS, H3, Hdim, in_b + (size_t)ci * H3, 0);
            conv_split_kernel<<<(ROWS * Hdim) / 256, 256>>>(t1, conv_w + (size_t)ci * Hdim * KCONV,
                                                            conv_b + (size_t)ci * Hdim, ah, al);
            gemm(ah, al, wh + oo, wl + oo, x, ROWS, Hdim, Hdim, out_b + (size_t)ci * Hdim, x);
            rmsnorm_split_kernel<<<ROWS, 192>>>(x, c_ln2 + (size_t)ci * Hdim, ah, al, 0);
            gemm(ah, al, wh + ogu, wl + ogu, t12, ROWS, GUN, Hdim, 0, 0);
            silu_mul_split_kernel<<<(ROWS * IM / 4) / 256, 256>>>(t12, ah, al);
            gemm(ah, al, wh + od, wl + od, x, ROWS, Hdim, IM, 0, x);
            ci++;
        }
    }
    rmsnorm_split_kernel<<<ROWS, 192>>>(x, finln, ah, al, 1);
    {
        dim3 grid(ROWS / 128, VOCAB / 128);
        gemm_f16x2<<<grid, 256, SMEM_F16>>>((const unsigned short*)ah,
                                            (const unsigned short*)(wh + OFF_LM),
                                            (const unsigned short*)(wl + OFF_LM),
                                            (float*)d_out, ROWS, VOCAB, Hdim);
    }

    cudaEventDestroy(e1);
    cudaEventDestroy(e2);
    cudaStreamDestroy(s2);
}